// round 13
// baseline (speedup 1.0000x reference)
#include <cuda_runtime.h>
#include <cuda_bf16.h>
#include <cuda_fp16.h>
#include <math.h>
#include <stdint.h>

#define Bsz   8
#define Lsz   2048
#define Dsz   1024
#define BDsz  512
#define DINsz 1024
#define NSTsz 16
#define KCsz  4
#define DTRsz 32
#define Tsz   (Bsz*Lsz)   // 16384 tokens

#define CCH   32               // scan chunks
#define LCH   (Lsz/CCH)        // 64 steps per chunk
#define BDIM  (Bsz*DINsz)      // 8192 (b,d) channels

// ---------------- scratch (device globals; no allocation allowed) -------------
__device__ __align__(256) float g_xz  [Tsz*2*DINsz];
__device__ __align__(256) float g_xcs [Tsz*DINsz];
__device__ __align__(256) float g_xdbl[Tsz*64];
__device__ __align__(256) float g_dt  [Tsz*DINsz];
__device__ __align__(256) float g_m   [Tsz*BDsz];
// scan chunk scratch
__device__ __align__(256) float g_hloc[CCH*BDIM*NSTsz];
__device__ __align__(256) float g_S   [CCH*BDIM];
__device__ __align__(256) float g_Hs  [CCH*BDIM*NSTsz];
// fp16 activations
__device__ __align__(256) __half g_xh [Tsz*Dsz],   g_xl [Tsz*Dsz];   // x hi/lo
__device__ __align__(256) __half g_hh [Tsz*BDsz];                    // h single fp16
__device__ __align__(256) __half g_yh [Tsz*DINsz];                   // y single fp16
__device__ __align__(256) __half g_mh [Tsz*BDsz],  g_ml [Tsz*BDsz];  // ln(m) hi/lo
// fp16 transposed weights [N,K]
__device__ __align__(256) __half g_wd [BDsz*Dsz];
__device__ __align__(256) __half g_wi [2*DINsz*BDsz];
__device__ __align__(256) __half g_wo [BDsz*DINsz];
__device__ __align__(256) __half g_wu [Dsz*BDsz];

// ---------------- helpers ------------------------------------------------------
__device__ __forceinline__ float softplus_f(float v) {
    return v > 20.f ? v : log1pf(expf(v));
}
__device__ __forceinline__ void bf16split2(float x0, float x1, uint32_t& hi, uint32_t& lo) {
    uint32_t h;
    asm("cvt.rn.bf16x2.f32 %0, %1, %2;" : "=r"(h) : "f"(x1), "f"(x0));
    float g0 = __uint_as_float(h << 16);
    float g1 = __uint_as_float(h & 0xffff0000u);
    float l0 = x0 - g0, l1 = x1 - g1;
    uint32_t lw;
    asm("cvt.rn.bf16x2.f32 %0, %1, %2;" : "=r"(lw) : "f"(l1), "f"(l0));
    hi = h; lo = lw;
}
__device__ __forceinline__ void halfsplit2(float x0, float x1, uint32_t& hi, uint32_t& lo) {
    __half2 h2 = __floats2half2_rn(x0, x1);
    float2 g = __half22float2(h2);
    __half2 l2 = __floats2half2_rn(x0 - g.x, x1 - g.y);
    hi = *(uint32_t*)&h2;
    lo = *(uint32_t*)&l2;
}
__device__ __forceinline__ void mma_bf16(float* c, const uint32_t* a, const uint32_t* b) {
    asm volatile("mma.sync.aligned.m16n8k16.row.col.f32.bf16.bf16.f32 "
                 "{%0,%1,%2,%3}, {%4,%5,%6,%7}, {%8,%9}, {%0,%1,%2,%3};"
                 : "+f"(c[0]), "+f"(c[1]), "+f"(c[2]), "+f"(c[3])
                 : "r"(a[0]), "r"(a[1]), "r"(a[2]), "r"(a[3]), "r"(b[0]), "r"(b[1]));
}
__device__ __forceinline__ void mma_f16(float* c, const uint32_t* a, const uint32_t* b) {
    asm volatile("mma.sync.aligned.m16n8k16.row.col.f32.f16.f16.f32 "
                 "{%0,%1,%2,%3}, {%4,%5,%6,%7}, {%8,%9}, {%0,%1,%2,%3};"
                 : "+f"(c[0]), "+f"(c[1]), "+f"(c[2]), "+f"(c[3])
                 : "r"(a[0]), "r"(a[1]), "r"(a[2]), "r"(a[3]), "r"(b[0]), "r"(b[1]));
}
__device__ __forceinline__ void cp_async16(void* smem_dst, const void* gmem_src) {
    uint32_t daddr = (uint32_t)__cvta_generic_to_shared(smem_dst);
    asm volatile("cp.async.ca.shared.global [%0], [%1], 16;\n" :: "r"(daddr), "l"(gmem_src));
}
__device__ __forceinline__ uint32_t smem_u32(const void* p) {
    return (uint32_t)__cvta_generic_to_shared(p);
}
__device__ __forceinline__ void ldsm_x4(uint32_t& r0, uint32_t& r1, uint32_t& r2, uint32_t& r3,
                                        uint32_t addr) {
    asm volatile("ldmatrix.sync.aligned.m8n8.x4.shared.b16 {%0,%1,%2,%3}, [%4];"
                 : "=r"(r0), "=r"(r1), "=r"(r2), "=r"(r3) : "r"(addr));
}

// ========== fp16 GEMM: C[M,N] = A[M,K] @ B[N,K]^T ==============================
// XA=true:  A = Ah + Al (hi/lo pair), 2 MMAs per tile.
// XA=false: A = Ah single fp16, 1 MMA per tile.
// CTA 128x128, 4 warps (2x2), warp tile 64x64, BK=32, 3-stage safe pipeline.
// EPI: 0 fp32 out, 1 fp32+bias, 2 bias + single fp16 out
#define ASTRD 40   // b16 units per smem row (80B)
template<int EPI, bool XA>
__global__ void __launch_bounds__(128, 2) hx_gemm(
    int M, int N, int K,
    const __half* __restrict__ Ah, const __half* __restrict__ Al,
    const __half* __restrict__ B,
    const float* __restrict__ bias,
    float* __restrict__ C,
    __half* __restrict__ Ch)
{
    constexpr int BM = 128, BK = 32;
    constexpr int MT = 4, NT = 8;                 // warp = 64 x 64
    constexpr uint32_t TILE = BM * ASTRD * 2;     // 10240
    constexpr uint32_t A_HI = 0;
    constexpr uint32_t A_LO = TILE;               // only used if XA
    constexpr uint32_t B_T  = XA ? 2 * TILE : TILE;
    constexpr uint32_t STAGE = XA ? 3 * TILE : 2 * TILE;
    constexpr uint32_t OFF = 1024;

    extern __shared__ __align__(1024) char smem[];
    float* sBias = (float*)smem;

    const int tid = threadIdx.x, wid = tid >> 5, lane = tid & 31;
    const int bm = blockIdx.y * BM, bn = blockIdx.x * BM;
    const int wm = (wid & 1) * 64;
    const int wn = (wid >> 1) * 64;
    const int lr = lane >> 2, lc = lane & 3;

    if (EPI) sBias[tid] = __ldg(&bias[bn + tid]);   // 128 threads = BN

    float acc[MT][NT][4];
#pragma unroll
    for (int i = 0; i < MT; i++)
#pragma unroll
        for (int j = 0; j < NT; j++)
#pragma unroll
            for (int r = 0; r < 4; r++) acc[i][j][r] = 0.f;

    const uint32_t sb = smem_u32(smem) + OFF;

    // coalesced loader: 4 threads per 64B row-chunk
    auto issue = [&](int buf, int k0) {
        char* stg = smem + OFF + buf * STAGE;
#pragma unroll
        for (int i = 0; i < 4; i++) {
            int j = tid + i * 128;
            int r = j >> 2, c = j & 3;                  // row 0..127, 16B chunk
            uint32_t so = (uint32_t)r * (ASTRD * 2) + c * 16;
            size_t gA = ((size_t)(bm + r) * K + k0 + c * 8) * 2;
            size_t gB = ((size_t)(bn + r) * K + k0 + c * 8) * 2;
            cp_async16(stg + A_HI + so, (const char*)Ah + gA);
            if (XA) cp_async16(stg + A_LO + so, (const char*)Al + gA);
            cp_async16(stg + B_T + so, (const char*)B + gB);
        }
        asm volatile("cp.async.commit_group;\n");
    };

    // ldmatrix lane addressing
    const int a_row = lane & 15;
    const int a_kh = (lane >> 4) & 1;
    const int b_row = (lane & 7) + ((lane >> 4) & 1) * 8;
    const int b_kh = (lane >> 3) & 1;

    const int ntiles = K / BK;
    issue(0, 0);
    if (ntiles > 1) issue(1, BK);

    for (int kt = 0; kt < ntiles; kt++) {
        if (kt + 2 < ntiles) {
            issue((kt + 2) % 3, (kt + 2) * BK);
            asm volatile("cp.async.wait_group 2;\n");
        } else if (kt + 1 < ntiles) {
            asm volatile("cp.async.wait_group 1;\n");
        } else {
            asm volatile("cp.async.wait_group 0;\n");
        }
        __syncthreads();    // tile kt fully visible to all threads

        const uint32_t stg = sb + (kt % 3) * STAGE;

#pragma unroll
        for (int ks = 0; ks < 2; ks++) {
            const uint32_t kofs = ks * 32;             // bytes along k (16 halves)

            uint32_t bh[NT][2];
#pragma unroll
            for (int np = 0; np < 4; np++) {
                uint32_t ro = (uint32_t)(wn + np * 16 + b_row) * (ASTRD * 2) + kofs + b_kh * 16;
                ldsm_x4(bh[2 * np][0], bh[2 * np][1], bh[2 * np + 1][0], bh[2 * np + 1][1],
                        stg + B_T + ro);
            }
#pragma unroll
            for (int mt = 0; mt < MT; mt++) {
                uint32_t ro = (uint32_t)(wm + mt * 16 + a_row) * (ASTRD * 2) + kofs + a_kh * 16;
                uint32_t ah[4], al[4];
                ldsm_x4(ah[0], ah[1], ah[2], ah[3], stg + A_HI + ro);
                if (XA) ldsm_x4(al[0], al[1], al[2], al[3], stg + A_LO + ro);
#pragma unroll
                for (int nt = 0; nt < NT; nt++) {
                    mma_f16(acc[mt][nt], ah, bh[nt]);
                    if (XA) mma_f16(acc[mt][nt], al, bh[nt]);
                }
            }
        }
        __syncthreads();    // reads of stage kt done before overwrite
    }

#pragma unroll
    for (int mt = 0; mt < MT; mt++) {
        int row0 = bm + wm + mt * 16 + lr;
#pragma unroll
        for (int nt = 0; nt < NT; nt++) {
            int cb = wn + nt * 8 + lc * 2;
            int col = bn + cb;
            float o0 = acc[mt][nt][0], o1 = acc[mt][nt][1];
            float o2 = acc[mt][nt][2], o3 = acc[mt][nt][3];
            if (EPI >= 1) {
                float bb0 = sBias[cb], bb1 = sBias[cb + 1];
                o0 += bb0; o1 += bb1; o2 += bb0; o3 += bb1;
            }
            if (EPI == 2) {
                __half2 v01 = __floats2half2_rn(o0, o1);
                __half2 v23 = __floats2half2_rn(o2, o3);
                *(uint32_t*)&Ch[(size_t)row0 * N + col]       = *(uint32_t*)&v01;
                *(uint32_t*)&Ch[(size_t)(row0 + 8) * N + col] = *(uint32_t*)&v23;
            } else {
                *(float2*)&C[(size_t)row0 * N + col]       = make_float2(o0, o1);
                *(float2*)&C[(size_t)(row0 + 8) * N + col] = make_float2(o2, o3);
            }
        }
    }
}

// ================= prep kernels ================================================
__global__ void split_kernel(const float* __restrict__ s,
                             __half* __restrict__ h,
                             __half* __restrict__ l)
{
    int i = (blockIdx.x * blockDim.x + threadIdx.x) * 4;
    float4 v = *(const float4*)&s[i];
    uint32_t h0, l0, h1, l1;
    halfsplit2(v.x, v.y, h0, l0);
    halfsplit2(v.z, v.w, h1, l1);
    *(uint2*)&h[i] = make_uint2(h0, h1);
    *(uint2*)&l[i] = make_uint2(l0, l1);
}

__global__ void tsplit_kernel(const float* __restrict__ W,
                              __half* __restrict__ Th,
                              int K, int N)
{
    __shared__ float t[32][33];
    int n0 = blockIdx.x * 32, k0 = blockIdx.y * 32;
    int tx = threadIdx.x, ty = threadIdx.y;
    for (int i = ty; i < 32; i += 8)
        t[i][tx] = W[(size_t)(k0 + i) * N + n0 + tx];
    __syncthreads();
    for (int i = ty; i < 32; i += 8)
        Th[(size_t)(n0 + i) * K + k0 + tx] = __float2half(t[tx][i]);
}

// ================= warp-MMA fp32-in GEMM (small GEMMs 4 & 5) ===================
template<int BN, int WM, int EPI>
__global__ void __launch_bounds__(256, 2) mma_gemm(
    int M, int N, int K, int lda, int ldb, int ldc,
    const float* __restrict__ A, const float* __restrict__ B,
    const float* __restrict__ bias, float* __restrict__ C)
{
    constexpr int BM = 128, BK = 16;
    constexpr int WARPS_M = BM / WM;
    constexpr int WARPS_N = 8 / WARPS_M;
    constexpr int WN = BN / WARPS_N;
    constexpr int MT = WM / 16;
    constexpr int NT = WN / 8;
    constexpr int ASTR = BK + 4;
    constexpr int BSTR = BN + 4;

    __shared__ float As[2][BM * ASTR];
    __shared__ float Bs[2][BK * BSTR];

    const int tid = threadIdx.x;
    const int bm = blockIdx.y * BM;
    const int bn = blockIdx.x * BN;
    const int wid = tid >> 5, lane = tid & 31;
    const int wm = (wid % WARPS_M) * WM;
    const int wn = (wid / WARPS_M) * WN;
    const int lr = lane >> 2;
    const int lc = lane & 3;

    float acc[MT][NT][4];
#pragma unroll
    for (int i = 0; i < MT; i++)
#pragma unroll
        for (int j = 0; j < NT; j++)
#pragma unroll
            for (int r = 0; r < 4; r++) acc[i][j][r] = 0.f;

    const int ntiles = K / BK;

    auto issue = [&](int buf, int k0) {
#pragma unroll
        for (int i = 0; i < 2; i++) {
            int j = tid + i * 256;
            int r = j >> 2, c4 = (j & 3) << 2;
            cp_async16(&As[buf][r * ASTR + c4], &A[(size_t)(bm + r) * lda + k0 + c4]);
        }
        constexpr int BF4 = BK * BN / 4;
#pragma unroll
        for (int i = 0; i < BF4 / 256 + (BF4 % 256 ? 1 : 0); i++) {
            int j = tid + i * 256;
            if (BF4 % 256 == 0 || j < BF4) {
                int k = j / (BN / 4), n4 = (j % (BN / 4)) << 2;
                cp_async16(&Bs[buf][k * BSTR + n4], &B[(size_t)(k0 + k) * ldb + bn + n4]);
            }
        }
        asm volatile("cp.async.commit_group;\n");
    };

    issue(0, 0);
    for (int kt = 0; kt < ntiles; kt++) {
        if (kt + 1 < ntiles) {
            issue((kt + 1) & 1, (kt + 1) * BK);
            asm volatile("cp.async.wait_group 1;\n");
        } else {
            asm volatile("cp.async.wait_group 0;\n");
        }
        __syncthreads();

        const float* as = As[kt & 1];
        const float* bs = Bs[kt & 1];

        uint32_t ahi[MT][4], alo[MT][4];
#pragma unroll
        for (int mt = 0; mt < MT; mt++) {
            int m0 = wm + mt * 16 + lr;
            float2 f00 = *(const float2*)&as[m0 * ASTR + 2 * lc];
            float2 f10 = *(const float2*)&as[(m0 + 8) * ASTR + 2 * lc];
            float2 f01 = *(const float2*)&as[m0 * ASTR + 2 * lc + 8];
            float2 f11 = *(const float2*)&as[(m0 + 8) * ASTR + 2 * lc + 8];
            bf16split2(f00.x, f00.y, ahi[mt][0], alo[mt][0]);
            bf16split2(f10.x, f10.y, ahi[mt][1], alo[mt][1]);
            bf16split2(f01.x, f01.y, ahi[mt][2], alo[mt][2]);
            bf16split2(f11.x, f11.y, ahi[mt][3], alo[mt][3]);
        }
        uint32_t bhi[NT][2], blo[NT][2];
#pragma unroll
        for (int nt = 0; nt < NT; nt++) {
            int n0 = wn + nt * 8 + lr;
            float fb0 = bs[(2 * lc) * BSTR + n0];
            float fb1 = bs[(2 * lc + 1) * BSTR + n0];
            float fb2 = bs[(2 * lc + 8) * BSTR + n0];
            float fb3 = bs[(2 * lc + 9) * BSTR + n0];
            bf16split2(fb0, fb1, bhi[nt][0], blo[nt][0]);
            bf16split2(fb2, fb3, bhi[nt][1], blo[nt][1]);
        }
#pragma unroll
        for (int mt = 0; mt < MT; mt++)
#pragma unroll
            for (int nt = 0; nt < NT; nt++) {
                mma_bf16(acc[mt][nt], ahi[mt], bhi[nt]);
                mma_bf16(acc[mt][nt], ahi[mt], blo[nt]);
                mma_bf16(acc[mt][nt], alo[mt], bhi[nt]);
            }
        __syncthreads();
    }

#pragma unroll
    for (int mt = 0; mt < MT; mt++) {
        int row0 = bm + wm + mt * 16 + lr;
#pragma unroll
        for (int nt = 0; nt < NT; nt++) {
            int col = bn + wn + nt * 8 + lc * 2;
            float o0 = acc[mt][nt][0], o1 = acc[mt][nt][1];
            float o2 = acc[mt][nt][2], o3 = acc[mt][nt][3];
            if (EPI >= 1) {
                float bb0 = __ldg(&bias[col]), bb1 = __ldg(&bias[col + 1]);
                o0 += bb0; o1 += bb1; o2 += bb0; o3 += bb1;
            }
            if (EPI == 2) {
                o0 = softplus_f(o0); o1 = softplus_f(o1);
                o2 = softplus_f(o2); o3 = softplus_f(o3);
            }
            *(float2*)&C[(size_t)row0 * ldc + col]       = make_float2(o0, o1);
            *(float2*)&C[(size_t)(row0 + 8) * ldc + col] = make_float2(o2, o3);
        }
    }
}

// ---------------- causal depthwise conv (K=4) + SiLU --------------------------
__global__ void conv_silu_kernel(const float* __restrict__ xz,
                                 const float* __restrict__ conv_w,
                                 const float* __restrict__ conv_b,
                                 float* __restrict__ out)
{
    int idx = blockIdx.x * blockDim.x + threadIdx.x;
    int d = idx & (DINsz - 1);
    int t = idx >> 10;
    int l = t & (Lsz - 1);

    float acc = __ldg(&conv_b[d]);
#pragma unroll
    for (int k = 0; k < KCsz; k++) {
        int ls = l + k - (KCsz - 1);
        if (ls >= 0)
            acc = fmaf(xz[(size_t)(t + k - (KCsz - 1)) * (2 * DINsz) + d],
                       __ldg(&conv_w[d * KCsz + k]), acc);
    }
    float s = 1.f / (1.f + expf(-acc));
    out[idx] = acc * s;
}

// ================= chunked selective scan ======================================
__global__ void scan_chunk_kernel(const float* __restrict__ dt,
                                  const float* __restrict__ xdbl,
                                  const float* __restrict__ xcs,
                                  const float* __restrict__ A_log)
{
    const int b = blockIdx.y, c = blockIdx.z;
    const int lane = threadIdx.x;
    const int d = blockIdx.x * 32 + lane;
    const int bd = b * DINsz + d;

    float An[NSTsz];
#pragma unroll
    for (int n = 0; n < NSTsz; n++) An[n] = -expf(A_log[d * NSTsz + n]);
    const float An0 = An[0];
    bool geo = true;
#pragma unroll
    for (int n = 0; n < NSTsz; n++) {
        float want = An0 * (n + 1);
        if (fabsf(An[n] - want) > 1e-5f * fabsf(want)) geo = false;
    }

    float h[NSTsz];
#pragma unroll
    for (int n = 0; n < NSTsz; n++) h[n] = 0.f;
    float S = 0.f;

    __shared__ float sB[32];
    const int t0 = b * Lsz + c * LCH;

    if (geo) {
        for (int l = 0; l < LCH; l++) {
            const int t = t0 + l;
            sB[lane] = xdbl[(size_t)t * 64 + DTRsz + lane];
            const float dtv = dt[(size_t)t * DINsz + d];
            const float xv  = xcs[(size_t)t * DINsz + d];
            __syncwarp();
            const float dtx = dtv * xv;
            const float r = __expf(dtv * An0);
            float p = r;
#pragma unroll
            for (int n = 0; n < NSTsz; n++) {
                h[n] = fmaf(h[n], p, dtx * sB[n]);
                p *= r;
            }
            S += dtv;
            __syncwarp();
        }
    } else {
        for (int l = 0; l < LCH; l++) {
            const int t = t0 + l;
            sB[lane] = xdbl[(size_t)t * 64 + DTRsz + lane];
            const float dtv = dt[(size_t)t * DINsz + d];
            const float xv  = xcs[(size_t)t * DINsz + d];
            __syncwarp();
            const float dtx = dtv * xv;
#pragma unroll
            for (int n = 0; n < NSTsz; n++)
                h[n] = fmaf(h[n], __expf(dtv * An[n]), dtx * sB[n]);
            S += dtv;
            __syncwarp();
        }
    }

    float* o = &g_hloc[((size_t)c * BDIM + bd) * NSTsz];
#pragma unroll
    for (int n = 0; n < NSTsz; n++) o[n] = h[n];
    g_S[(size_t)c * BDIM + bd] = S;
}

__global__ void scan_combine_kernel(const float* __restrict__ A_log)
{
    const int bd = blockIdx.x * blockDim.x + threadIdx.x;
    const int d = bd & (DINsz - 1);

    float An[NSTsz];
#pragma unroll
    for (int n = 0; n < NSTsz; n++) An[n] = -expf(A_log[d * NSTsz + n]);
    const float An0 = An[0];
    bool geo = true;
#pragma unroll
    for (int n = 0; n < NSTsz; n++) {
        float want = An0 * (n + 1);
        if (fabsf(An[n] - want) > 1e-5f * fabsf(want)) geo = false;
    }

    float H[NSTsz];
#pragma unroll
    for (int n = 0; n < NSTsz; n++) H[n] = 0.f;

    for (int c = 0; c < CCH; c++) {
        float* hs = &g_Hs[((size_t)c * BDIM + bd) * NSTsz];
#pragma unroll
        for (int n = 0; n < NSTsz; n++) hs[n] = H[n];

        const float S = g_S[(size_t)c * BDIM + bd];
        const float* hl = &g_hloc[((size_t)c * BDIM + bd) * NSTsz];
        if (geo) {
            const float R = __expf(S * An0);
            float p = R;
#pragma unroll
            for (int n = 0; n < NSTsz; n++) {
                H[n] = fmaf(H[n], p, hl[n]);
                p *= R;
            }
        } else {
#pragma unroll
            for (int n = 0; n < NSTsz; n++)
                H[n] = fmaf(H[n], __expf(S * An[n]), hl[n]);
        }
    }
}

__global__ void scan_final_kernel(const float* __restrict__ dt,
                                  const float* __restrict__ xdbl,
                                  const float* __restrict__ xcs,
                                  const float* __restrict__ xz,
                                  const float* __restrict__ A_log,
                                  const float* __restrict__ D_skip,
                                  __half* __restrict__ yh)
{
    const int b = blockIdx.y, c = blockIdx.z;
    const int lane = threadIdx.x;
    const int d = blockIdx.x * 32 + lane;
    const int bd = b * DINsz + d;

    float An[NSTsz];
#pragma unroll
    for (int n = 0; n < NSTsz; n++) An[n] = -expf(A_log[d * NSTsz + n]);
    const float An0 = An[0];
    bool geo = true;
#pragma unroll
    for (int n = 0; n < NSTsz; n++) {
        float want = An0 * (n + 1);
        if (fabsf(An[n] - want) > 1e-5f * fabsf(want)) geo = false;
    }

    float h[NSTsz];
    const float* hs = &g_Hs[((size_t)c * BDIM + bd) * NSTsz];
#pragma unroll
    for (int n = 0; n < NSTsz; n++) h[n] = hs[n];

    const float Dv = D_skip[d];
    __shared__ float sBC[32];
    const int t0 = b * Lsz + c * LCH;

    for (int l = 0; l < LCH; l++) {
        const int t = t0 + l;
        sBC[lane] = xdbl[(size_t)t * 64 + DTRsz + lane];
        const float dtv = dt[(size_t)t * DINsz + d];
        const float xv  = xcs[(size_t)t * DINsz + d];
        const float zv  = xz[(size_t)t * (2 * DINsz) + DINsz + d];
        __syncwarp();
        const float dtx = dtv * xv;
        float yv = 0.f;
        if (geo) {
            const float r = __expf(dtv * An0);
            float p = r;
#pragma unroll
            for (int n = 0; n < NSTsz; n++) {
                h[n] = fmaf(h[n], p, dtx * sBC[n]);
                yv = fmaf(h[n], sBC[NSTsz + n], yv);
                p *= r;
            }
        } else {
#pragma unroll
            for (int n = 0; n < NSTsz; n++) {
                h[n] = fmaf(h[n], __expf(dtv * An[n]), dtx * sBC[n]);
                yv = fmaf(h[n], sBC[NSTsz + n], yv);
            }
        }
        const float sz = zv / (1.f + __expf(-zv));
        const float o = (yv + Dv * xv) * sz;
        yh[(size_t)t * DINsz + d] = __float2half(o);
        __syncwarp();
    }
}

// ---------------- LayerNorm(512): fp32 in -> hi/lo fp16 out --------------------
__global__ void ln_kernel(const float* __restrict__ m,
                          const float* __restrict__ g,
                          const float* __restrict__ b,
                          __half* __restrict__ oh,
                          __half* __restrict__ ol)
{
    const int warp = threadIdx.x >> 5;
    const int lane = threadIdx.x & 31;
    const int row = blockIdx.x * 8 + warp;

    const float4* p = (const float4*)(m + (size_t)row * BDsz);
    float4 v[4];
    float s = 0.f, ss = 0.f;
#pragma unroll
    for (int i = 0; i < 4; i++) {
        v[i] = p[lane + i * 32];
        s  += v[i].x + v[i].y + v[i].z + v[i].w;
        ss += v[i].x * v[i].x + v[i].y * v[i].y + v[i].z * v[i].z + v[i].w * v[i].w;
    }
#pragma unroll
    for (int o = 16; o > 0; o >>= 1) {
        s  += __shfl_xor_sync(0xFFFFFFFF, s, o);
        ss += __shfl_xor_sync(0xFFFFFFFF, ss, o);
    }
    const float mu = s * (1.f / BDsz);
    const float var = ss * (1.f / BDsz) - mu * mu;
    const float r = rsqrtf(var + 1e-5f);
#pragma unroll
    for (int i = 0; i < 4; i++) {
        int col = (lane + i * 32) * 4;
        float o0 = (v[i].x - mu) * r * __ldg(&g[col + 0]) + __ldg(&b[col + 0]);
        float o1 = (v[i].y - mu) * r * __ldg(&g[col + 1]) + __ldg(&b[col + 1]);
        float o2 = (v[i].z - mu) * r * __ldg(&g[col + 2]) + __ldg(&b[col + 2]);
        float o3 = (v[i].w - mu) * r * __ldg(&g[col + 3]) + __ldg(&b[col + 3]);
        uint32_t h0, l0, h1, l1;
        halfsplit2(o0, o1, h0, l0);
        halfsplit2(o2, o3, h1, l1);
        *(uint2*)&oh[(size_t)row * BDsz + col] = make_uint2(h0, h1);
        *(uint2*)&ol[(size_t)row * BDsz + col] = make_uint2(l0, l1);
    }
}

// ------------------------------- launch ---------------------------------------
extern "C" void kernel_launch(void* const* d_in, const int* in_sizes, int n_in,
                              void* d_out, int out_size)
{
    const float* x      = (const float*)d_in[0];
    const float* W_down = (const float*)d_in[1];
    const float* b_down = (const float*)d_in[2];
    const float* W_in   = (const float*)d_in[3];
    const float* conv_w = (const float*)d_in[4];
    const float* conv_b = (const float*)d_in[5];
    const float* W_x    = (const float*)d_in[6];
    const float* W_dt   = (const float*)d_in[7];
    const float* b_dt   = (const float*)d_in[8];
    const float* A_log  = (const float*)d_in[9];
    const float* D_skip = (const float*)d_in[10];
    const float* W_out  = (const float*)d_in[11];
    const float* ln_g   = (const float*)d_in[12];
    const float* ln_b   = (const float*)d_in[13];
    const float* W_up   = (const float*)d_in[14];
    const float* b_up   = (const float*)d_in[15];
    float* out = (float*)d_out;

    float *pxz, *pxcs, *pxdbl, *pdt, *pm;
    cudaGetSymbolAddress((void**)&pxz,   g_xz);
    cudaGetSymbolAddress((void**)&pxcs,  g_xcs);
    cudaGetSymbolAddress((void**)&pxdbl, g_xdbl);
    cudaGetSymbolAddress((void**)&pdt,   g_dt);
    cudaGetSymbolAddress((void**)&pm,    g_m);

    __half *pxh, *pxl, *phh, *pyh, *pmh, *pml;
    __half *pwd, *pwi, *pwo, *pwu;
    cudaGetSymbolAddress((void**)&pxh, g_xh);  cudaGetSymbolAddress((void**)&pxl, g_xl);
    cudaGetSymbolAddress((void**)&phh, g_hh);
    cudaGetSymbolAddress((void**)&pyh, g_yh);
    cudaGetSymbolAddress((void**)&pmh, g_mh);  cudaGetSymbolAddress((void**)&pml, g_ml);
    cudaGetSymbolAddress((void**)&pwd, g_wd);
    cudaGetSymbolAddress((void**)&pwi, g_wi);
    cudaGetSymbolAddress((void**)&pwo, g_wo);
    cudaGetSymbolAddress((void**)&pwu, g_wu);

    const int M = Tsz;
    const int SM_XA  = 1024 + 3 * 30720;   // 93184
    const int SM_SA  = 1024 + 3 * 20480;   // 62464
    cudaFuncSetAttribute((const void*)hx_gemm<2, true >, cudaFuncAttributeMaxDynamicSharedMemorySize, SM_XA);
    cudaFuncSetAttribute((const void*)hx_gemm<1, true >, cudaFuncAttributeMaxDynamicSharedMemorySize, SM_XA);
    cudaFuncSetAttribute((const void*)hx_gemm<0, false>, cudaFuncAttributeMaxDynamicSharedMemorySize, SM_SA);

    dim3 tb(32, 8);

    // launch order keeps a big GEMM at index 3 for ncu capture
    // 0) split x
    split_kernel<<<(Tsz * Dsz) / (256 * 4), 256>>>(x, pxh, pxl);
    // 1) W_down^T
    tsplit_kernel<<<dim3(BDsz / 32, Dsz / 32), tb>>>(W_down, pwd, Dsz, BDsz);
    // 2) W_in^T
    tsplit_kernel<<<dim3(2 * DINsz / 32, BDsz / 32), tb>>>(W_in, pwi, BDsz, 2 * DINsz);

    // 3) GEMM1 (x2-A): h = x @ W_down + b_down -> single fp16   [PROFILED]
    hx_gemm<2, true><<<dim3(BDsz / 128, M / 128), 128, SM_XA>>>(
        M, BDsz, Dsz, pxh, pxl, pwd, b_down, nullptr, phh);

    // 4) W_out^T, 5) W_up^T
    tsplit_kernel<<<dim3(BDsz / 32, DINsz / 32), tb>>>(W_out, pwo, DINsz, BDsz);
    tsplit_kernel<<<dim3(Dsz / 32, BDsz / 32), tb>>>(W_up, pwu, BDsz, Dsz);

    // 6) GEMM2 (single-A): xz = h @ W_in -> fp32
    hx_gemm<0, false><<<dim3(2 * DINsz / 128, M / 128), 128, SM_SA>>>(
        M, 2 * DINsz, BDsz, phh, nullptr, pwi, nullptr, pxz, nullptr);

    // 7) conv + silu -> xcs
    conv_silu_kernel<<<(Tsz * DINsz) / 256, 256>>>(pxz, conv_w, conv_b, pxcs);

    // 8) x_dbl = xcs @ W_x
    mma_gemm<64, 32, 0><<<dim3(1, M / 128), 256>>>(
        M, 64, DINsz, DINsz, 64, 64, pxcs, W_x, nullptr, pxdbl);

    // 9) dt = softplus(x_dbl[:, :32] @ W_dt + b_dt)
    mma_gemm<128, 64, 2><<<dim3(DINsz / 128, M / 128), 256>>>(
        M, DINsz, DTRsz, 64, DINsz, DINsz, pxdbl, W_dt, b_dt, pdt);

    // 10-12) chunked scan -> y single fp16
    scan_chunk_kernel<<<dim3(DINsz / 32, Bsz, CCH), 32>>>(pdt, pxdbl, pxcs, A_log);
    scan_combine_kernel<<<BDIM / 256, 256>>>(A_log);
    scan_final_kernel<<<dim3(DINsz / 32, Bsz, CCH), 32>>>(
        pdt, pxdbl, pxcs, pxz, A_log, D_skip, pyh);

    // 13) GEMM7 (single-A): m = y @ W_out -> fp32
    hx_gemm<0, false><<<dim3(BDsz / 128, M / 128), 128, SM_SA>>>(
        M, BDsz, DINsz, pyh, nullptr, pwo, nullptr, pm, nullptr);

    // 14) LayerNorm -> hi/lo fp16
    ln_kernel<<<M / 8, 256>>>(pm, ln_g, ln_b, pmh, pml);

    // 15) GEMM9 (x2-A): out = m_ln @ W_up + b_up -> fp32
    hx_gemm<1, true><<<dim3(Dsz / 128, M / 128), 128, SM_XA>>>(
        M, Dsz, BDsz, pmh, pml, pwu, b_up, out, nullptr);
}

// round 16
// speedup vs baseline: 1.4250x; 1.4250x over previous
#include <cuda_runtime.h>
#include <cuda_bf16.h>
#include <cuda_fp16.h>
#include <math.h>
#include <stdint.h>

#define Bsz   8
#define Lsz   2048
#define Dsz   1024
#define BDsz  512
#define DINsz 1024
#define NSTsz 16
#define KCsz  4
#define DTRsz 32
#define Tsz   (Bsz*Lsz)   // 16384 tokens

#define CCH   32               // scan chunks
#define LCH   (Lsz/CCH)        // 64 steps per chunk
#define BDIM  (Bsz*DINsz)      // 8192 (b,d) channels

// ---------------- scratch (device globals; no allocation allowed) -------------
__device__ __align__(256) float g_xz  [Tsz*2*DINsz];
__device__ __align__(256) float g_xcs [Tsz*DINsz];
__device__ __align__(256) float g_xdbl[Tsz*64];
__device__ __align__(256) float g_dt  [Tsz*DINsz];
__device__ __align__(256) float g_m   [Tsz*BDsz];
// scan chunk scratch
__device__ __align__(256) float g_hloc[CCH*BDIM*NSTsz];
__device__ __align__(256) float g_S   [CCH*BDIM];
__device__ __align__(256) float g_Hs  [CCH*BDIM*NSTsz];
// fp16 activations
__device__ __align__(256) __half g_xh [Tsz*Dsz],   g_xl [Tsz*Dsz];   // x hi/lo
__device__ __align__(256) __half g_hh [Tsz*BDsz];                    // h single fp16
__device__ __align__(256) __half g_yh [Tsz*DINsz];                   // y single fp16
__device__ __align__(256) __half g_mh [Tsz*BDsz],  g_ml [Tsz*BDsz];  // ln(m) hi/lo
// fp16 transposed weights [N,K]
__device__ __align__(256) __half g_wd [BDsz*Dsz];
__device__ __align__(256) __half g_wi [2*DINsz*BDsz];
__device__ __align__(256) __half g_wo [BDsz*DINsz];
__device__ __align__(256) __half g_wu [Dsz*BDsz];

// ---------------- helpers ------------------------------------------------------
__device__ __forceinline__ float softplus_f(float v) {
    return v > 20.f ? v : log1pf(expf(v));
}
__device__ __forceinline__ void bf16split2(float x0, float x1, uint32_t& hi, uint32_t& lo) {
    uint32_t h;
    asm("cvt.rn.bf16x2.f32 %0, %1, %2;" : "=r"(h) : "f"(x1), "f"(x0));
    float g0 = __uint_as_float(h << 16);
    float g1 = __uint_as_float(h & 0xffff0000u);
    float l0 = x0 - g0, l1 = x1 - g1;
    uint32_t lw;
    asm("cvt.rn.bf16x2.f32 %0, %1, %2;" : "=r"(lw) : "f"(l1), "f"(l0));
    hi = h; lo = lw;
}
__device__ __forceinline__ void halfsplit2(float x0, float x1, uint32_t& hi, uint32_t& lo) {
    __half2 h2 = __floats2half2_rn(x0, x1);
    float2 g = __half22float2(h2);
    __half2 l2 = __floats2half2_rn(x0 - g.x, x1 - g.y);
    hi = *(uint32_t*)&h2;
    lo = *(uint32_t*)&l2;
}
__device__ __forceinline__ void mma_bf16(float* c, const uint32_t* a, const uint32_t* b) {
    asm volatile("mma.sync.aligned.m16n8k16.row.col.f32.bf16.bf16.f32 "
                 "{%0,%1,%2,%3}, {%4,%5,%6,%7}, {%8,%9}, {%0,%1,%2,%3};"
                 : "+f"(c[0]), "+f"(c[1]), "+f"(c[2]), "+f"(c[3])
                 : "r"(a[0]), "r"(a[1]), "r"(a[2]), "r"(a[3]), "r"(b[0]), "r"(b[1]));
}
__device__ __forceinline__ void mma_f16(float* c, const uint32_t* a, const uint32_t* b) {
    asm volatile("mma.sync.aligned.m16n8k16.row.col.f32.f16.f16.f32 "
                 "{%0,%1,%2,%3}, {%4,%5,%6,%7}, {%8,%9}, {%0,%1,%2,%3};"
                 : "+f"(c[0]), "+f"(c[1]), "+f"(c[2]), "+f"(c[3])
                 : "r"(a[0]), "r"(a[1]), "r"(a[2]), "r"(a[3]), "r"(b[0]), "r"(b[1]));
}
__device__ __forceinline__ void cp_async16(void* smem_dst, const void* gmem_src) {
    uint32_t daddr = (uint32_t)__cvta_generic_to_shared(smem_dst);
    asm volatile("cp.async.ca.shared.global [%0], [%1], 16;\n" :: "r"(daddr), "l"(gmem_src));
}
__device__ __forceinline__ uint32_t smem_u32(const void* p) {
    return (uint32_t)__cvta_generic_to_shared(p);
}
__device__ __forceinline__ void ldsm_x4(uint32_t& r0, uint32_t& r1, uint32_t& r2, uint32_t& r3,
                                        uint32_t addr) {
    asm volatile("ldmatrix.sync.aligned.m8n8.x4.shared.b16 {%0,%1,%2,%3}, [%4];"
                 : "=r"(r0), "=r"(r1), "=r"(r2), "=r"(r3) : "r"(addr));
}

// ========== fp16 GEMM: C[M,N] = A[M,K] @ B[N,K]^T ==============================
// XA=true:  A = Ah + Al (hi/lo pair), 2 MMAs per tile.
// XA=false: A = Ah single fp16, 1 MMA per tile.
// CTA 128x128, 4 warps (2x2), warp tile 64x64, BK=32, 3-stage ring.
// SINGLE-barrier safe ordering: wait_group -> barrier -> issue -> consume.
//   RAW: every thread's wait for tile kt precedes the barrier, so after the
//        barrier tile kt is fully visible to all threads.
//   WAR: issue targets stage (kt+2)%3 == (kt-1)%3, whose reads all completed
//        in iteration kt-1, strictly before this iteration's barrier.
// EPI: 0 fp32 out, 1 fp32+bias, 2 bias + single fp16 out
#define ASTRD 40   // b16 units per smem row (80B)
template<int EPI, bool XA>
__global__ void __launch_bounds__(128, 2) hx_gemm(
    int M, int N, int K,
    const __half* __restrict__ Ah, const __half* __restrict__ Al,
    const __half* __restrict__ B,
    const float* __restrict__ bias,
    float* __restrict__ C,
    __half* __restrict__ Ch)
{
    constexpr int BM = 128, BK = 32;
    constexpr int MT = 4, NT = 8;                 // warp = 64 x 64
    constexpr uint32_t TILE = BM * ASTRD * 2;     // 10240
    constexpr uint32_t A_HI = 0;
    constexpr uint32_t A_LO = TILE;               // only used if XA
    constexpr uint32_t B_T  = XA ? 2 * TILE : TILE;
    constexpr uint32_t STAGE = XA ? 3 * TILE : 2 * TILE;
    constexpr uint32_t OFF = 1024;

    extern __shared__ __align__(1024) char smem[];
    float* sBias = (float*)smem;

    const int tid = threadIdx.x, wid = tid >> 5, lane = tid & 31;
    const int bm = blockIdx.y * BM, bn = blockIdx.x * BM;
    const int wm = (wid & 1) * 64;
    const int wn = (wid >> 1) * 64;
    const int lr = lane >> 2, lc = lane & 3;

    if (EPI) sBias[tid] = __ldg(&bias[bn + tid]);   // 128 threads = BN

    float acc[MT][NT][4];
#pragma unroll
    for (int i = 0; i < MT; i++)
#pragma unroll
        for (int j = 0; j < NT; j++)
#pragma unroll
            for (int r = 0; r < 4; r++) acc[i][j][r] = 0.f;

    const uint32_t sb = smem_u32(smem) + OFF;

    // coalesced loader: 4 threads per 64B row-chunk
    auto issue = [&](int buf, int k0) {
        char* stg = smem + OFF + buf * STAGE;
#pragma unroll
        for (int i = 0; i < 4; i++) {
            int j = tid + i * 128;
            int r = j >> 2, c = j & 3;                  // row 0..127, 16B chunk
            uint32_t so = (uint32_t)r * (ASTRD * 2) + c * 16;
            size_t gA = ((size_t)(bm + r) * K + k0 + c * 8) * 2;
            size_t gB = ((size_t)(bn + r) * K + k0 + c * 8) * 2;
            cp_async16(stg + A_HI + so, (const char*)Ah + gA);
            if (XA) cp_async16(stg + A_LO + so, (const char*)Al + gA);
            cp_async16(stg + B_T + so, (const char*)B + gB);
        }
        asm volatile("cp.async.commit_group;\n");
    };

    // ldmatrix lane addressing
    const int a_row = lane & 15;
    const int a_kh = (lane >> 4) & 1;
    const int b_row = (lane & 7) + ((lane >> 4) & 1) * 8;
    const int b_kh = (lane >> 3) & 1;

    const int ntiles = K / BK;
    issue(0, 0);
    if (ntiles > 1) issue(1, BK);

    for (int kt = 0; kt < ntiles; kt++) {
        // ensure this thread's groups for tile kt are complete
        if (kt + 1 < ntiles) {
            asm volatile("cp.async.wait_group 1;\n");
        } else {
            asm volatile("cp.async.wait_group 0;\n");
        }
        __syncthreads();    // all waits done -> tile kt visible; reads of (kt-1) done
        if (kt + 2 < ntiles)
            issue((kt + 2) % 3, (kt + 2) * BK);   // writes stage (kt-1)%3: WAR-safe

        const uint32_t stg = sb + (kt % 3) * STAGE;

#pragma unroll
        for (int ks = 0; ks < 2; ks++) {
            const uint32_t kofs = ks * 32;             // bytes along k (16 halves)

            uint32_t bh[NT][2];
#pragma unroll
            for (int np = 0; np < 4; np++) {
                uint32_t ro = (uint32_t)(wn + np * 16 + b_row) * (ASTRD * 2) + kofs + b_kh * 16;
                ldsm_x4(bh[2 * np][0], bh[2 * np][1], bh[2 * np + 1][0], bh[2 * np + 1][1],
                        stg + B_T + ro);
            }
#pragma unroll
            for (int mt = 0; mt < MT; mt++) {
                uint32_t ro = (uint32_t)(wm + mt * 16 + a_row) * (ASTRD * 2) + kofs + a_kh * 16;
                uint32_t ah[4], al[4];
                ldsm_x4(ah[0], ah[1], ah[2], ah[3], stg + A_HI + ro);
                if (XA) ldsm_x4(al[0], al[1], al[2], al[3], stg + A_LO + ro);
#pragma unroll
                for (int nt = 0; nt < NT; nt++) {
                    mma_f16(acc[mt][nt], ah, bh[nt]);
                    if (XA) mma_f16(acc[mt][nt], al, bh[nt]);
                }
            }
        }
    }

#pragma unroll
    for (int mt = 0; mt < MT; mt++) {
        int row0 = bm + wm + mt * 16 + lr;
#pragma unroll
        for (int nt = 0; nt < NT; nt++) {
            int cb = wn + nt * 8 + lc * 2;
            int col = bn + cb;
            float o0 = acc[mt][nt][0], o1 = acc[mt][nt][1];
            float o2 = acc[mt][nt][2], o3 = acc[mt][nt][3];
            if (EPI >= 1) {
                float bb0 = sBias[cb], bb1 = sBias[cb + 1];
                o0 += bb0; o1 += bb1; o2 += bb0; o3 += bb1;
            }
            if (EPI == 2) {
                __half2 v01 = __floats2half2_rn(o0, o1);
                __half2 v23 = __floats2half2_rn(o2, o3);
                *(uint32_t*)&Ch[(size_t)row0 * N + col]       = *(uint32_t*)&v01;
                *(uint32_t*)&Ch[(size_t)(row0 + 8) * N + col] = *(uint32_t*)&v23;
            } else {
                *(float2*)&C[(size_t)row0 * N + col]       = make_float2(o0, o1);
                *(float2*)&C[(size_t)(row0 + 8) * N + col] = make_float2(o2, o3);
            }
        }
    }
}

// ================= prep kernels ================================================
__global__ void split_kernel(const float* __restrict__ s,
                             __half* __restrict__ h,
                             __half* __restrict__ l)
{
    int i = (blockIdx.x * blockDim.x + threadIdx.x) * 4;
    float4 v = *(const float4*)&s[i];
    uint32_t h0, l0, h1, l1;
    halfsplit2(v.x, v.y, h0, l0);
    halfsplit2(v.z, v.w, h1, l1);
    *(uint2*)&h[i] = make_uint2(h0, h1);
    *(uint2*)&l[i] = make_uint2(l0, l1);
}

__global__ void tsplit_kernel(const float* __restrict__ W,
                              __half* __restrict__ Th,
                              int K, int N)
{
    __shared__ float t[32][33];
    int n0 = blockIdx.x * 32, k0 = blockIdx.y * 32;
    int tx = threadIdx.x, ty = threadIdx.y;
    for (int i = ty; i < 32; i += 8)
        t[i][tx] = W[(size_t)(k0 + i) * N + n0 + tx];
    __syncthreads();
    for (int i = ty; i < 32; i += 8)
        Th[(size_t)(n0 + i) * K + k0 + tx] = __float2half(t[tx][i]);
}

// ================= warp-MMA fp32-in GEMM (small GEMMs 4 & 5) ===================
template<int BN, int WM, int EPI>
__global__ void __launch_bounds__(256, 2) mma_gemm(
    int M, int N, int K, int lda, int ldb, int ldc,
    const float* __restrict__ A, const float* __restrict__ B,
    const float* __restrict__ bias, float* __restrict__ C)
{
    constexpr int BM = 128, BK = 16;
    constexpr int WARPS_M = BM / WM;
    constexpr int WARPS_N = 8 / WARPS_M;
    constexpr int WN = BN / WARPS_N;
    constexpr int MT = WM / 16;
    constexpr int NT = WN / 8;
    constexpr int ASTR = BK + 4;
    constexpr int BSTR = BN + 4;

    __shared__ float As[2][BM * ASTR];
    __shared__ float Bs[2][BK * BSTR];

    const int tid = threadIdx.x;
    const int bm = blockIdx.y * BM;
    const int bn = blockIdx.x * BN;
    const int wid = tid >> 5, lane = tid & 31;
    const int wm = (wid % WARPS_M) * WM;
    const int wn = (wid / WARPS_M) * WN;
    const int lr = lane >> 2;
    const int lc = lane & 3;

    float acc[MT][NT][4];
#pragma unroll
    for (int i = 0; i < MT; i++)
#pragma unroll
        for (int j = 0; j < NT; j++)
#pragma unroll
            for (int r = 0; r < 4; r++) acc[i][j][r] = 0.f;

    const int ntiles = K / BK;

    auto issue = [&](int buf, int k0) {
#pragma unroll
        for (int i = 0; i < 2; i++) {
            int j = tid + i * 256;
            int r = j >> 2, c4 = (j & 3) << 2;
            cp_async16(&As[buf][r * ASTR + c4], &A[(size_t)(bm + r) * lda + k0 + c4]);
        }
        constexpr int BF4 = BK * BN / 4;
#pragma unroll
        for (int i = 0; i < BF4 / 256 + (BF4 % 256 ? 1 : 0); i++) {
            int j = tid + i * 256;
            if (BF4 % 256 == 0 || j < BF4) {
                int k = j / (BN / 4), n4 = (j % (BN / 4)) << 2;
                cp_async16(&Bs[buf][k * BSTR + n4], &B[(size_t)(k0 + k) * ldb + bn + n4]);
            }
        }
        asm volatile("cp.async.commit_group;\n");
    };

    issue(0, 0);
    for (int kt = 0; kt < ntiles; kt++) {
        if (kt + 1 < ntiles) {
            issue((kt + 1) & 1, (kt + 1) * BK);
            asm volatile("cp.async.wait_group 1;\n");
        } else {
            asm volatile("cp.async.wait_group 0;\n");
        }
        __syncthreads();

        const float* as = As[kt & 1];
        const float* bs = Bs[kt & 1];

        uint32_t ahi[MT][4], alo[MT][4];
#pragma unroll
        for (int mt = 0; mt < MT; mt++) {
            int m0 = wm + mt * 16 + lr;
            float2 f00 = *(const float2*)&as[m0 * ASTR + 2 * lc];
            float2 f10 = *(const float2*)&as[(m0 + 8) * ASTR + 2 * lc];
            float2 f01 = *(const float2*)&as[m0 * ASTR + 2 * lc + 8];
            float2 f11 = *(const float2*)&as[(m0 + 8) * ASTR + 2 * lc + 8];
            bf16split2(f00.x, f00.y, ahi[mt][0], alo[mt][0]);
            bf16split2(f10.x, f10.y, ahi[mt][1], alo[mt][1]);
            bf16split2(f01.x, f01.y, ahi[mt][2], alo[mt][2]);
            bf16split2(f11.x, f11.y, ahi[mt][3], alo[mt][3]);
        }
        uint32_t bhi[NT][2], blo[NT][2];
#pragma unroll
        for (int nt = 0; nt < NT; nt++) {
            int n0 = wn + nt * 8 + lr;
            float fb0 = bs[(2 * lc) * BSTR + n0];
            float fb1 = bs[(2 * lc + 1) * BSTR + n0];
            float fb2 = bs[(2 * lc + 8) * BSTR + n0];
            float fb3 = bs[(2 * lc + 9) * BSTR + n0];
            bf16split2(fb0, fb1, bhi[nt][0], blo[nt][0]);
            bf16split2(fb2, fb3, bhi[nt][1], blo[nt][1]);
        }
#pragma unroll
        for (int mt = 0; mt < MT; mt++)
#pragma unroll
            for (int nt = 0; nt < NT; nt++) {
                mma_bf16(acc[mt][nt], ahi[mt], bhi[nt]);
                mma_bf16(acc[mt][nt], ahi[mt], blo[nt]);
                mma_bf16(acc[mt][nt], alo[mt], bhi[nt]);
            }
        __syncthreads();
    }

#pragma unroll
    for (int mt = 0; mt < MT; mt++) {
        int row0 = bm + wm + mt * 16 + lr;
#pragma unroll
        for (int nt = 0; nt < NT; nt++) {
            int col = bn + wn + nt * 8 + lc * 2;
            float o0 = acc[mt][nt][0], o1 = acc[mt][nt][1];
            float o2 = acc[mt][nt][2], o3 = acc[mt][nt][3];
            if (EPI >= 1) {
                float bb0 = __ldg(&bias[col]), bb1 = __ldg(&bias[col + 1]);
                o0 += bb0; o1 += bb1; o2 += bb0; o3 += bb1;
            }
            if (EPI == 2) {
                o0 = softplus_f(o0); o1 = softplus_f(o1);
                o2 = softplus_f(o2); o3 = softplus_f(o3);
            }
            *(float2*)&C[(size_t)row0 * ldc + col]       = make_float2(o0, o1);
            *(float2*)&C[(size_t)(row0 + 8) * ldc + col] = make_float2(o2, o3);
        }
    }
}

// ---------------- causal depthwise conv (K=4) + SiLU --------------------------
__global__ void conv_silu_kernel(const float* __restrict__ xz,
                                 const float* __restrict__ conv_w,
                                 const float* __restrict__ conv_b,
                                 float* __restrict__ out)
{
    int idx = blockIdx.x * blockDim.x + threadIdx.x;
    int d = idx & (DINsz - 1);
    int t = idx >> 10;
    int l = t & (Lsz - 1);

    float acc = __ldg(&conv_b[d]);
#pragma unroll
    for (int k = 0; k < KCsz; k++) {
        int ls = l + k - (KCsz - 1);
        if (ls >= 0)
            acc = fmaf(xz[(size_t)(t + k - (KCsz - 1)) * (2 * DINsz) + d],
                       __ldg(&conv_w[d * KCsz + k]), acc);
    }
    float s = 1.f / (1.f + expf(-acc));
    out[idx] = acc * s;
}

// ================= chunked selective scan ======================================
__global__ void scan_chunk_kernel(const float* __restrict__ dt,
                                  const float* __restrict__ xdbl,
                                  const float* __restrict__ xcs,
                                  const float* __restrict__ A_log)
{
    const int b = blockIdx.y, c = blockIdx.z;
    const int lane = threadIdx.x;
    const int d = blockIdx.x * 32 + lane;
    const int bd = b * DINsz + d;

    float An[NSTsz];
#pragma unroll
    for (int n = 0; n < NSTsz; n++) An[n] = -expf(A_log[d * NSTsz + n]);
    const float An0 = An[0];
    bool geo = true;
#pragma unroll
    for (int n = 0; n < NSTsz; n++) {
        float want = An0 * (n + 1);
        if (fabsf(An[n] - want) > 1e-5f * fabsf(want)) geo = false;
    }

    float h[NSTsz];
#pragma unroll
    for (int n = 0; n < NSTsz; n++) h[n] = 0.f;
    float S = 0.f;

    __shared__ float sB[32];
    const int t0 = b * Lsz + c * LCH;

    if (geo) {
        for (int l = 0; l < LCH; l++) {
            const int t = t0 + l;
            sB[lane] = xdbl[(size_t)t * 64 + DTRsz + lane];
            const float dtv = dt[(size_t)t * DINsz + d];
            const float xv  = xcs[(size_t)t * DINsz + d];
            __syncwarp();
            const float dtx = dtv * xv;
            const float r = __expf(dtv * An0);
            float p = r;
#pragma unroll
            for (int n = 0; n < NSTsz; n++) {
                h[n] = fmaf(h[n], p, dtx * sB[n]);
                p *= r;
            }
            S += dtv;
            __syncwarp();
        }
    } else {
        for (int l = 0; l < LCH; l++) {
            const int t = t0 + l;
            sB[lane] = xdbl[(size_t)t * 64 + DTRsz + lane];
            const float dtv = dt[(size_t)t * DINsz + d];
            const float xv  = xcs[(size_t)t * DINsz + d];
            __syncwarp();
            const float dtx = dtv * xv;
#pragma unroll
            for (int n = 0; n < NSTsz; n++)
                h[n] = fmaf(h[n], __expf(dtv * An[n]), dtx * sB[n]);
            S += dtv;
            __syncwarp();
        }
    }

    float* o = &g_hloc[((size_t)c * BDIM + bd) * NSTsz];
#pragma unroll
    for (int n = 0; n < NSTsz; n++) o[n] = h[n];
    g_S[(size_t)c * BDIM + bd] = S;
}

__global__ void scan_combine_kernel(const float* __restrict__ A_log)
{
    const int bd = blockIdx.x * blockDim.x + threadIdx.x;
    const int d = bd & (DINsz - 1);

    float An[NSTsz];
#pragma unroll
    for (int n = 0; n < NSTsz; n++) An[n] = -expf(A_log[d * NSTsz + n]);
    const float An0 = An[0];
    bool geo = true;
#pragma unroll
    for (int n = 0; n < NSTsz; n++) {
        float want = An0 * (n + 1);
        if (fabsf(An[n] - want) > 1e-5f * fabsf(want)) geo = false;
    }

    float H[NSTsz];
#pragma unroll
    for (int n = 0; n < NSTsz; n++) H[n] = 0.f;

    for (int c = 0; c < CCH; c++) {
        float* hs = &g_Hs[((size_t)c * BDIM + bd) * NSTsz];
#pragma unroll
        for (int n = 0; n < NSTsz; n++) hs[n] = H[n];

        const float S = g_S[(size_t)c * BDIM + bd];
        const float* hl = &g_hloc[((size_t)c * BDIM + bd) * NSTsz];
        if (geo) {
            const float R = __expf(S * An0);
            float p = R;
#pragma unroll
            for (int n = 0; n < NSTsz; n++) {
                H[n] = fmaf(H[n], p, hl[n]);
                p *= R;
            }
        } else {
#pragma unroll
            for (int n = 0; n < NSTsz; n++)
                H[n] = fmaf(H[n], __expf(S * An[n]), hl[n]);
        }
    }
}

__global__ void scan_final_kernel(const float* __restrict__ dt,
                                  const float* __restrict__ xdbl,
                                  const float* __restrict__ xcs,
                                  const float* __restrict__ xz,
                                  const float* __restrict__ A_log,
                                  const float* __restrict__ D_skip,
                                  __half* __restrict__ yh)
{
    const int b = blockIdx.y, c = blockIdx.z;
    const int lane = threadIdx.x;
    const int d = blockIdx.x * 32 + lane;
    const int bd = b * DINsz + d;

    float An[NSTsz];
#pragma unroll
    for (int n = 0; n < NSTsz; n++) An[n] = -expf(A_log[d * NSTsz + n]);
    const float An0 = An[0];
    bool geo = true;
#pragma unroll
    for (int n = 0; n < NSTsz; n++) {
        float want = An0 * (n + 1);
        if (fabsf(An[n] - want) > 1e-5f * fabsf(want)) geo = false;
    }

    float h[NSTsz];
    const float* hs = &g_Hs[((size_t)c * BDIM + bd) * NSTsz];
#pragma unroll
    for (int n = 0; n < NSTsz; n++) h[n] = hs[n];

    const float Dv = D_skip[d];
    __shared__ float sBC[32];
    const int t0 = b * Lsz + c * LCH;

    for (int l = 0; l < LCH; l++) {
        const int t = t0 + l;
        sBC[lane] = xdbl[(size_t)t * 64 + DTRsz + lane];
        const float dtv = dt[(size_t)t * DINsz + d];
        const float xv  = xcs[(size_t)t * DINsz + d];
        const float zv  = xz[(size_t)t * (2 * DINsz) + DINsz + d];
        __syncwarp();
        const float dtx = dtv * xv;
        float yv = 0.f;
        if (geo) {
            const float r = __expf(dtv * An0);
            float p = r;
#pragma unroll
            for (int n = 0; n < NSTsz; n++) {
                h[n] = fmaf(h[n], p, dtx * sBC[n]);
                yv = fmaf(h[n], sBC[NSTsz + n], yv);
                p *= r;
            }
        } else {
#pragma unroll
            for (int n = 0; n < NSTsz; n++) {
                h[n] = fmaf(h[n], __expf(dtv * An[n]), dtx * sBC[n]);
                yv = fmaf(h[n], sBC[NSTsz + n], yv);
            }
        }
        const float sz = zv / (1.f + __expf(-zv));
        const float o = (yv + Dv * xv) * sz;
        yh[(size_t)t * DINsz + d] = __float2half(o);
        __syncwarp();
    }
}

// ---------------- LayerNorm(512): fp32 in -> hi/lo fp16 out --------------------
__global__ void ln_kernel(const float* __restrict__ m,
                          const float* __restrict__ g,
                          const float* __restrict__ b,
                          __half* __restrict__ oh,
                          __half* __restrict__ ol)
{
    const int warp = threadIdx.x >> 5;
    const int lane = threadIdx.x & 31;
    const int row = blockIdx.x * 8 + warp;

    const float4* p = (const float4*)(m + (size_t)row * BDsz);
    float4 v[4];
    float s = 0.f, ss = 0.f;
#pragma unroll
    for (int i = 0; i < 4; i++) {
        v[i] = p[lane + i * 32];
        s  += v[i].x + v[i].y + v[i].z + v[i].w;
        ss += v[i].x * v[i].x + v[i].y * v[i].y + v[i].z * v[i].z + v[i].w * v[i].w;
    }
#pragma unroll
    for (int o = 16; o > 0; o >>= 1) {
        s  += __shfl_xor_sync(0xFFFFFFFF, s, o);
        ss += __shfl_xor_sync(0xFFFFFFFF, ss, o);
    }
    const float mu = s * (1.f / BDsz);
    const float var = ss * (1.f / BDsz) - mu * mu;
    const float r = rsqrtf(var + 1e-5f);
#pragma unroll
    for (int i = 0; i < 4; i++) {
        int col = (lane + i * 32) * 4;
        float o0 = (v[i].x - mu) * r * __ldg(&g[col + 0]) + __ldg(&b[col + 0]);
        float o1 = (v[i].y - mu) * r * __ldg(&g[col + 1]) + __ldg(&b[col + 1]);
        float o2 = (v[i].z - mu) * r * __ldg(&g[col + 2]) + __ldg(&b[col + 2]);
        float o3 = (v[i].w - mu) * r * __ldg(&g[col + 3]) + __ldg(&b[col + 3]);
        uint32_t h0, l0, h1, l1;
        halfsplit2(o0, o1, h0, l0);
        halfsplit2(o2, o3, h1, l1);
        *(uint2*)&oh[(size_t)row * BDsz + col] = make_uint2(h0, h1);
        *(uint2*)&ol[(size_t)row * BDsz + col] = make_uint2(l0, l1);
    }
}

// ------------------------------- launch ---------------------------------------
extern "C" void kernel_launch(void* const* d_in, const int* in_sizes, int n_in,
                              void* d_out, int out_size)
{
    const float* x      = (const float*)d_in[0];
    const float* W_down = (const float*)d_in[1];
    const float* b_down = (const float*)d_in[2];
    const float* W_in   = (const float*)d_in[3];
    const float* conv_w = (const float*)d_in[4];
    const float* conv_b = (const float*)d_in[5];
    const float* W_x    = (const float*)d_in[6];
    const float* W_dt   = (const float*)d_in[7];
    const float* b_dt   = (const float*)d_in[8];
    const float* A_log  = (const float*)d_in[9];
    const float* D_skip = (const float*)d_in[10];
    const float* W_out  = (const float*)d_in[11];
    const float* ln_g   = (const float*)d_in[12];
    const float* ln_b   = (const float*)d_in[13];
    const float* W_up   = (const float*)d_in[14];
    const float* b_up   = (const float*)d_in[15];
    float* out = (float*)d_out;

    float *pxz, *pxcs, *pxdbl, *pdt, *pm;
    cudaGetSymbolAddress((void**)&pxz,   g_xz);
    cudaGetSymbolAddress((void**)&pxcs,  g_xcs);
    cudaGetSymbolAddress((void**)&pxdbl, g_xdbl);
    cudaGetSymbolAddress((void**)&pdt,   g_dt);
    cudaGetSymbolAddress((void**)&pm,    g_m);

    __half *pxh, *pxl, *phh, *pyh, *pmh, *pml;
    __half *pwd, *pwi, *pwo, *pwu;
    cudaGetSymbolAddress((void**)&pxh, g_xh);  cudaGetSymbolAddress((void**)&pxl, g_xl);
    cudaGetSymbolAddress((void**)&phh, g_hh);
    cudaGetSymbolAddress((void**)&pyh, g_yh);
    cudaGetSymbolAddress((void**)&pmh, g_mh);  cudaGetSymbolAddress((void**)&pml, g_ml);
    cudaGetSymbolAddress((void**)&pwd, g_wd);
    cudaGetSymbolAddress((void**)&pwi, g_wi);
    cudaGetSymbolAddress((void**)&pwo, g_wo);
    cudaGetSymbolAddress((void**)&pwu, g_wu);

    const int M = Tsz;
    const int SM_XA  = 1024 + 3 * 30720;   // 93184
    const int SM_SA  = 1024 + 3 * 20480;   // 62464
    cudaFuncSetAttribute((const void*)hx_gemm<2, true >, cudaFuncAttributeMaxDynamicSharedMemorySize, SM_XA);
    cudaFuncSetAttribute((const void*)hx_gemm<1, true >, cudaFuncAttributeMaxDynamicSharedMemorySize, SM_XA);
    cudaFuncSetAttribute((const void*)hx_gemm<0, false>, cudaFuncAttributeMaxDynamicSharedMemorySize, SM_SA);

    dim3 tb(32, 8);

    // launch order keeps a big GEMM at index 3 for ncu capture
    // 0) split x
    split_kernel<<<(Tsz * Dsz) / (256 * 4), 256>>>(x, pxh, pxl);
    // 1) W_down^T
    tsplit_kernel<<<dim3(BDsz / 32, Dsz / 32), tb>>>(W_down, pwd, Dsz, BDsz);
    // 2) W_in^T
    tsplit_kernel<<<dim3(2 * DINsz / 32, BDsz / 32), tb>>>(W_in, pwi, BDsz, 2 * DINsz);

    // 3) GEMM1 (x2-A): h = x @ W_down + b_down -> single fp16   [PROFILED]
    hx_gemm<2, true><<<dim3(BDsz / 128, M / 128), 128, SM_XA>>>(
        M, BDsz, Dsz, pxh, pxl, pwd, b_down, nullptr, phh);

    // 4) W_out^T, 5) W_up^T
    tsplit_kernel<<<dim3(BDsz / 32, DINsz / 32), tb>>>(W_out, pwo, DINsz, BDsz);
    tsplit_kernel<<<dim3(Dsz / 32, BDsz / 32), tb>>>(W_up, pwu, BDsz, Dsz);

    // 6) GEMM2 (single-A): xz = h @ W_in -> fp32
    hx_gemm<0, false><<<dim3(2 * DINsz / 128, M / 128), 128, SM_SA>>>(
        M, 2 * DINsz, BDsz, phh, nullptr, pwi, nullptr, pxz, nullptr);

    // 7) conv + silu -> xcs
    conv_silu_kernel<<<(Tsz * DINsz) / 256, 256>>>(pxz, conv_w, conv_b, pxcs);

    // 8) x_dbl = xcs @ W_x
    mma_gemm<64, 32, 0><<<dim3(1, M / 128), 256>>>(
        M, 64, DINsz, DINsz, 64, 64, pxcs, W_x, nullptr, pxdbl);

    // 9) dt = softplus(x_dbl[:, :32] @ W_dt + b_dt)
    mma_gemm<128, 64, 2><<<dim3(DINsz / 128, M / 128), 256>>>(
        M, DINsz, DTRsz, 64, DINsz, DINsz, pxdbl, W_dt, b_dt, pdt);

    // 10-12) chunked scan -> y single fp16
    scan_chunk_kernel<<<dim3(DINsz / 32, Bsz, CCH), 32>>>(pdt, pxdbl, pxcs, A_log);
    scan_combine_kernel<<<BDIM / 256, 256>>>(A_log);
    scan_final_kernel<<<dim3(DINsz / 32, Bsz, CCH), 32>>>(
        pdt, pxdbl, pxcs, pxz, A_log, D_skip, pyh);

    // 13) GEMM7 (single-A): m = y @ W_out -> fp32
    hx_gemm<0, false><<<dim3(BDsz / 128, M / 128), 128, SM_SA>>>(
        M, BDsz, DINsz, pyh, nullptr, pwo, nullptr, pm, nullptr);

    // 14) LayerNorm -> hi/lo fp16
    ln_kernel<<<M / 8, 256>>>(pm, ln_g, ln_b, pmh, pml);

    // 15) GEMM9 (x2-A): out = m_ln @ W_up + b_up -> fp32
    hx_gemm<1, true><<<dim3(Dsz / 128, M / 128), 128, SM_XA>>>(
        M, Dsz, BDsz, pmh, pml, pwu, b_up, out, nullptr);
}

// round 17
// speedup vs baseline: 1.5995x; 1.1224x over previous
#include <cuda_runtime.h>
#include <cuda_bf16.h>
#include <cuda_fp16.h>
#include <math.h>
#include <stdint.h>

#define Bsz   8
#define Lsz   2048
#define Dsz   1024
#define BDsz  512
#define DINsz 1024
#define NSTsz 16
#define KCsz  4
#define DTRsz 32
#define Tsz   (Bsz*Lsz)   // 16384 tokens

#define CCH   32               // scan chunks
#define LCH   (Lsz/CCH)        // 64 steps per chunk
#define BDIM  (Bsz*DINsz)      // 8192 (b,d) channels

// ---------------- scratch (device globals; no allocation allowed) -------------
__device__ __align__(256) float g_xz  [Tsz*2*DINsz];
__device__ __align__(256) float g_xcs [Tsz*DINsz];
__device__ __align__(256) float g_xdbl[Tsz*64];
__device__ __align__(256) float g_dt  [Tsz*DINsz];
__device__ __align__(256) float g_m   [Tsz*BDsz];
// scan chunk scratch
__device__ __align__(256) float g_hloc[CCH*BDIM*NSTsz];
__device__ __align__(256) float g_S   [CCH*BDIM];
__device__ __align__(256) float g_Hs  [CCH*BDIM*NSTsz];
// fp16 activations (single precision A operands)
__device__ __align__(256) __half g_xh [Tsz*Dsz];
__device__ __align__(256) __half g_hh [Tsz*BDsz];
__device__ __align__(256) __half g_yh [Tsz*DINsz];
__device__ __align__(256) __half g_mh [Tsz*BDsz];
// fp16 transposed weights [N,K]
__device__ __align__(256) __half g_wd [BDsz*Dsz];
__device__ __align__(256) __half g_wi [2*DINsz*BDsz];
__device__ __align__(256) __half g_wo [BDsz*DINsz];
__device__ __align__(256) __half g_wu [Dsz*BDsz];

// ---------------- helpers ------------------------------------------------------
__device__ __forceinline__ float softplus_f(float v) {
    return v > 20.f ? v : log1pf(expf(v));
}
__device__ __forceinline__ void bf16split2(float x0, float x1, uint32_t& hi, uint32_t& lo) {
    uint32_t h;
    asm("cvt.rn.bf16x2.f32 %0, %1, %2;" : "=r"(h) : "f"(x1), "f"(x0));
    float g0 = __uint_as_float(h << 16);
    float g1 = __uint_as_float(h & 0xffff0000u);
    float l0 = x0 - g0, l1 = x1 - g1;
    uint32_t lw;
    asm("cvt.rn.bf16x2.f32 %0, %1, %2;" : "=r"(lw) : "f"(l1), "f"(l0));
    hi = h; lo = lw;
}
__device__ __forceinline__ void mma_bf16(float* c, const uint32_t* a, const uint32_t* b) {
    asm volatile("mma.sync.aligned.m16n8k16.row.col.f32.bf16.bf16.f32 "
                 "{%0,%1,%2,%3}, {%4,%5,%6,%7}, {%8,%9}, {%0,%1,%2,%3};"
                 : "+f"(c[0]), "+f"(c[1]), "+f"(c[2]), "+f"(c[3])
                 : "r"(a[0]), "r"(a[1]), "r"(a[2]), "r"(a[3]), "r"(b[0]), "r"(b[1]));
}
__device__ __forceinline__ void mma_f16(float* c, const uint32_t* a, const uint32_t* b) {
    asm volatile("mma.sync.aligned.m16n8k16.row.col.f32.f16.f16.f32 "
                 "{%0,%1,%2,%3}, {%4,%5,%6,%7}, {%8,%9}, {%0,%1,%2,%3};"
                 : "+f"(c[0]), "+f"(c[1]), "+f"(c[2]), "+f"(c[3])
                 : "r"(a[0]), "r"(a[1]), "r"(a[2]), "r"(a[3]), "r"(b[0]), "r"(b[1]));
}
__device__ __forceinline__ void cp_async16(void* smem_dst, const void* gmem_src) {
    uint32_t daddr = (uint32_t)__cvta_generic_to_shared(smem_dst);
    asm volatile("cp.async.ca.shared.global [%0], [%1], 16;\n" :: "r"(daddr), "l"(gmem_src));
}
__device__ __forceinline__ uint32_t smem_u32(const void* p) {
    return (uint32_t)__cvta_generic_to_shared(p);
}
__device__ __forceinline__ void ldsm_x4(uint32_t& r0, uint32_t& r1, uint32_t& r2, uint32_t& r3,
                                        uint32_t addr) {
    asm volatile("ldmatrix.sync.aligned.m8n8.x4.shared.b16 {%0,%1,%2,%3}, [%4];"
                 : "=r"(r0), "=r"(r1), "=r"(r2), "=r"(r3) : "r"(addr));
}

// ========== fp16 GEMM: C[M,N] = A[M,K] @ B[N,K]^T (single-A, 1 MMA/tile) =======
// CTA 128x128, 4 warps (2x2), warp tile 64x64, BK=32, 3-stage ring.
// SINGLE-barrier safe ordering: wait_group -> barrier -> issue -> consume.
//   RAW: every thread's wait for tile kt precedes the barrier.
//   WAR: issue targets stage (kt+2)%3 == (kt-1)%3, whose reads completed in
//        iteration kt-1, strictly before this iteration's barrier.
// EPI: 0 fp32 out, 1 fp32+bias, 2 bias + single fp16 out
#define ASTRD 40   // b16 units per smem row (80B)
template<int EPI>
__global__ void __launch_bounds__(128, 2) hx_gemm(
    int M, int N, int K,
    const __half* __restrict__ Ah,
    const __half* __restrict__ B,
    const float* __restrict__ bias,
    float* __restrict__ C,
    __half* __restrict__ Ch)
{
    constexpr int BM = 128, BK = 32;
    constexpr int MT = 4, NT = 8;                 // warp = 64 x 64
    constexpr uint32_t TILE = BM * ASTRD * 2;     // 10240
    constexpr uint32_t A_HI = 0;
    constexpr uint32_t B_T  = TILE;
    constexpr uint32_t STAGE = 2 * TILE;          // 20480
    constexpr uint32_t OFF = 1024;

    extern __shared__ __align__(1024) char smem[];
    float* sBias = (float*)smem;

    const int tid = threadIdx.x, wid = tid >> 5, lane = tid & 31;
    const int bm = blockIdx.y * BM, bn = blockIdx.x * BM;
    const int wm = (wid & 1) * 64;
    const int wn = (wid >> 1) * 64;
    const int lr = lane >> 2, lc = lane & 3;

    if (EPI) sBias[tid] = __ldg(&bias[bn + tid]);   // 128 threads = BN

    float acc[MT][NT][4];
#pragma unroll
    for (int i = 0; i < MT; i++)
#pragma unroll
        for (int j = 0; j < NT; j++)
#pragma unroll
            for (int r = 0; r < 4; r++) acc[i][j][r] = 0.f;

    const uint32_t sb = smem_u32(smem) + OFF;

    // coalesced loader: 4 threads per 64B row-chunk
    auto issue = [&](int buf, int k0) {
        char* stg = smem + OFF + buf * STAGE;
#pragma unroll
        for (int i = 0; i < 4; i++) {
            int j = tid + i * 128;
            int r = j >> 2, c = j & 3;                  // row 0..127, 16B chunk
            uint32_t so = (uint32_t)r * (ASTRD * 2) + c * 16;
            size_t gA = ((size_t)(bm + r) * K + k0 + c * 8) * 2;
            size_t gB = ((size_t)(bn + r) * K + k0 + c * 8) * 2;
            cp_async16(stg + A_HI + so, (const char*)Ah + gA);
            cp_async16(stg + B_T + so, (const char*)B + gB);
        }
        asm volatile("cp.async.commit_group;\n");
    };

    // ldmatrix lane addressing
    const int a_row = lane & 15;
    const int a_kh = (lane >> 4) & 1;
    const int b_row = (lane & 7) + ((lane >> 4) & 1) * 8;
    const int b_kh = (lane >> 3) & 1;

    const int ntiles = K / BK;
    issue(0, 0);
    if (ntiles > 1) issue(1, BK);

    for (int kt = 0; kt < ntiles; kt++) {
        if (kt + 1 < ntiles) {
            asm volatile("cp.async.wait_group 1;\n");
        } else {
            asm volatile("cp.async.wait_group 0;\n");
        }
        __syncthreads();    // tile kt visible; reads of (kt-1) done
        if (kt + 2 < ntiles)
            issue((kt + 2) % 3, (kt + 2) * BK);   // writes stage (kt-1)%3: WAR-safe

        const uint32_t stg = sb + (kt % 3) * STAGE;

#pragma unroll
        for (int ks = 0; ks < 2; ks++) {
            const uint32_t kofs = ks * 32;             // bytes along k (16 halves)

            uint32_t bh[NT][2];
#pragma unroll
            for (int np = 0; np < 4; np++) {
                uint32_t ro = (uint32_t)(wn + np * 16 + b_row) * (ASTRD * 2) + kofs + b_kh * 16;
                ldsm_x4(bh[2 * np][0], bh[2 * np][1], bh[2 * np + 1][0], bh[2 * np + 1][1],
                        stg + B_T + ro);
            }
#pragma unroll
            for (int mt = 0; mt < MT; mt++) {
                uint32_t ro = (uint32_t)(wm + mt * 16 + a_row) * (ASTRD * 2) + kofs + a_kh * 16;
                uint32_t ah[4];
                ldsm_x4(ah[0], ah[1], ah[2], ah[3], stg + A_HI + ro);
#pragma unroll
                for (int nt = 0; nt < NT; nt++)
                    mma_f16(acc[mt][nt], ah, bh[nt]);
            }
        }
    }

#pragma unroll
    for (int mt = 0; mt < MT; mt++) {
        int row0 = bm + wm + mt * 16 + lr;
#pragma unroll
        for (int nt = 0; nt < NT; nt++) {
            int cb = wn + nt * 8 + lc * 2;
            int col = bn + cb;
            float o0 = acc[mt][nt][0], o1 = acc[mt][nt][1];
            float o2 = acc[mt][nt][2], o3 = acc[mt][nt][3];
            if (EPI >= 1) {
                float bb0 = sBias[cb], bb1 = sBias[cb + 1];
                o0 += bb0; o1 += bb1; o2 += bb0; o3 += bb1;
            }
            if (EPI == 2) {
                __half2 v01 = __floats2half2_rn(o0, o1);
                __half2 v23 = __floats2half2_rn(o2, o3);
                *(uint32_t*)&Ch[(size_t)row0 * N + col]       = *(uint32_t*)&v01;
                *(uint32_t*)&Ch[(size_t)(row0 + 8) * N + col] = *(uint32_t*)&v23;
            } else {
                *(float2*)&C[(size_t)row0 * N + col]       = make_float2(o0, o1);
                *(float2*)&C[(size_t)(row0 + 8) * N + col] = make_float2(o2, o3);
            }
        }
    }
}

// ================= prep kernels ================================================
__global__ void split_kernel(const float* __restrict__ s,
                             __half* __restrict__ h)
{
    int i = (blockIdx.x * blockDim.x + threadIdx.x) * 4;
    float4 v = *(const float4*)&s[i];
    __half2 h01 = __floats2half2_rn(v.x, v.y);
    __half2 h23 = __floats2half2_rn(v.z, v.w);
    *(uint2*)&h[i] = make_uint2(*(uint32_t*)&h01, *(uint32_t*)&h23);
}

// transpose W[K,N] fp32 -> T[N,K] single fp16
__global__ void tsplit_kernel(const float* __restrict__ W,
                              __half* __restrict__ Th,
                              int K, int N)
{
    __shared__ float t[32][33];
    int n0 = blockIdx.x * 32, k0 = blockIdx.y * 32;
    int tx = threadIdx.x, ty = threadIdx.y;
    for (int i = ty; i < 32; i += 8)
        t[i][tx] = W[(size_t)(k0 + i) * N + n0 + tx];
    __syncthreads();
    for (int i = ty; i < 32; i += 8)
        Th[(size_t)(n0 + i) * K + k0 + tx] = __float2half(t[tx][i]);
}

// ================= warp-MMA fp32-in GEMM (small GEMMs 4 & 5) ===================
template<int BN, int WM, int EPI>
__global__ void __launch_bounds__(256, 2) mma_gemm(
    int M, int N, int K, int lda, int ldb, int ldc,
    const float* __restrict__ A, const float* __restrict__ B,
    const float* __restrict__ bias, float* __restrict__ C)
{
    constexpr int BM = 128, BK = 16;
    constexpr int WARPS_M = BM / WM;
    constexpr int WARPS_N = 8 / WARPS_M;
    constexpr int WN = BN / WARPS_N;
    constexpr int MT = WM / 16;
    constexpr int NT = WN / 8;
    constexpr int ASTR = BK + 4;
    constexpr int BSTR = BN + 4;

    __shared__ float As[2][BM * ASTR];
    __shared__ float Bs[2][BK * BSTR];

    const int tid = threadIdx.x;
    const int bm = blockIdx.y * BM;
    const int bn = blockIdx.x * BN;
    const int wid = tid >> 5, lane = tid & 31;
    const int wm = (wid % WARPS_M) * WM;
    const int wn = (wid / WARPS_M) * WN;
    const int lr = lane >> 2;
    const int lc = lane & 3;

    float acc[MT][NT][4];
#pragma unroll
    for (int i = 0; i < MT; i++)
#pragma unroll
        for (int j = 0; j < NT; j++)
#pragma unroll
            for (int r = 0; r < 4; r++) acc[i][j][r] = 0.f;

    const int ntiles = K / BK;

    auto issue = [&](int buf, int k0) {
#pragma unroll
        for (int i = 0; i < 2; i++) {
            int j = tid + i * 256;
            int r = j >> 2, c4 = (j & 3) << 2;
            cp_async16(&As[buf][r * ASTR + c4], &A[(size_t)(bm + r) * lda + k0 + c4]);
        }
        constexpr int BF4 = BK * BN / 4;
#pragma unroll
        for (int i = 0; i < BF4 / 256 + (BF4 % 256 ? 1 : 0); i++) {
            int j = tid + i * 256;
            if (BF4 % 256 == 0 || j < BF4) {
                int k = j / (BN / 4), n4 = (j % (BN / 4)) << 2;
                cp_async16(&Bs[buf][k * BSTR + n4], &B[(size_t)(k0 + k) * ldb + bn + n4]);
            }
        }
        asm volatile("cp.async.commit_group;\n");
    };

    issue(0, 0);
    for (int kt = 0; kt < ntiles; kt++) {
        if (kt + 1 < ntiles) {
            issue((kt + 1) & 1, (kt + 1) * BK);
            asm volatile("cp.async.wait_group 1;\n");
        } else {
            asm volatile("cp.async.wait_group 0;\n");
        }
        __syncthreads();

        const float* as = As[kt & 1];
        const float* bs = Bs[kt & 1];

        uint32_t ahi[MT][4], alo[MT][4];
#pragma unroll
        for (int mt = 0; mt < MT; mt++) {
            int m0 = wm + mt * 16 + lr;
            float2 f00 = *(const float2*)&as[m0 * ASTR + 2 * lc];
            float2 f10 = *(const float2*)&as[(m0 + 8) * ASTR + 2 * lc];
            float2 f01 = *(const float2*)&as[m0 * ASTR + 2 * lc + 8];
            float2 f11 = *(const float2*)&as[(m0 + 8) * ASTR + 2 * lc + 8];
            bf16split2(f00.x, f00.y, ahi[mt][0], alo[mt][0]);
            bf16split2(f10.x, f10.y, ahi[mt][1], alo[mt][1]);
            bf16split2(f01.x, f01.y, ahi[mt][2], alo[mt][2]);
            bf16split2(f11.x, f11.y, ahi[mt][3], alo[mt][3]);
        }
        uint32_t bhi[NT][2], blo[NT][2];
#pragma unroll
        for (int nt = 0; nt < NT; nt++) {
            int n0 = wn + nt * 8 + lr;
            float fb0 = bs[(2 * lc) * BSTR + n0];
            float fb1 = bs[(2 * lc + 1) * BSTR + n0];
            float fb2 = bs[(2 * lc + 8) * BSTR + n0];
            float fb3 = bs[(2 * lc + 9) * BSTR + n0];
            bf16split2(fb0, fb1, bhi[nt][0], blo[nt][0]);
            bf16split2(fb2, fb3, bhi[nt][1], blo[nt][1]);
        }
#pragma unroll
        for (int mt = 0; mt < MT; mt++)
#pragma unroll
            for (int nt = 0; nt < NT; nt++) {
                mma_bf16(acc[mt][nt], ahi[mt], bhi[nt]);
                mma_bf16(acc[mt][nt], ahi[mt], blo[nt]);
                mma_bf16(acc[mt][nt], alo[mt], bhi[nt]);
            }
        __syncthreads();
    }

#pragma unroll
    for (int mt = 0; mt < MT; mt++) {
        int row0 = bm + wm + mt * 16 + lr;
#pragma unroll
        for (int nt = 0; nt < NT; nt++) {
            int col = bn + wn + nt * 8 + lc * 2;
            float o0 = acc[mt][nt][0], o1 = acc[mt][nt][1];
            float o2 = acc[mt][nt][2], o3 = acc[mt][nt][3];
            if (EPI >= 1) {
                float bb0 = __ldg(&bias[col]), bb1 = __ldg(&bias[col + 1]);
                o0 += bb0; o1 += bb1; o2 += bb0; o3 += bb1;
            }
            if (EPI == 2) {
                o0 = softplus_f(o0); o1 = softplus_f(o1);
                o2 = softplus_f(o2); o3 = softplus_f(o3);
            }
            *(float2*)&C[(size_t)row0 * ldc + col]       = make_float2(o0, o1);
            *(float2*)&C[(size_t)(row0 + 8) * ldc + col] = make_float2(o2, o3);
        }
    }
}

// ---------------- causal depthwise conv (K=4) + SiLU --------------------------
__global__ void conv_silu_kernel(const float* __restrict__ xz,
                                 const float* __restrict__ conv_w,
                                 const float* __restrict__ conv_b,
                                 float* __restrict__ out)
{
    int idx = blockIdx.x * blockDim.x + threadIdx.x;
    int d = idx & (DINsz - 1);
    int t = idx >> 10;
    int l = t & (Lsz - 1);

    float acc = __ldg(&conv_b[d]);
#pragma unroll
    for (int k = 0; k < KCsz; k++) {
        int ls = l + k - (KCsz - 1);
        if (ls >= 0)
            acc = fmaf(xz[(size_t)(t + k - (KCsz - 1)) * (2 * DINsz) + d],
                       __ldg(&conv_w[d * KCsz + k]), acc);
    }
    float s = 1.f / (1.f + expf(-acc));
    out[idx] = acc * s;
}

// ================= chunked selective scan ======================================
__global__ void scan_chunk_kernel(const float* __restrict__ dt,
                                  const float* __restrict__ xdbl,
                                  const float* __restrict__ xcs,
                                  const float* __restrict__ A_log)
{
    const int b = blockIdx.y, c = blockIdx.z;
    const int lane = threadIdx.x;
    const int d = blockIdx.x * 32 + lane;
    const int bd = b * DINsz + d;

    float An[NSTsz];
#pragma unroll
    for (int n = 0; n < NSTsz; n++) An[n] = -expf(A_log[d * NSTsz + n]);
    const float An0 = An[0];
    bool geo = true;
#pragma unroll
    for (int n = 0; n < NSTsz; n++) {
        float want = An0 * (n + 1);
        if (fabsf(An[n] - want) > 1e-5f * fabsf(want)) geo = false;
    }

    float h[NSTsz];
#pragma unroll
    for (int n = 0; n < NSTsz; n++) h[n] = 0.f;
    float S = 0.f;

    __shared__ float sB[32];
    const int t0 = b * Lsz + c * LCH;

    if (geo) {
        for (int l = 0; l < LCH; l++) {
            const int t = t0 + l;
            sB[lane] = xdbl[(size_t)t * 64 + DTRsz + lane];
            const float dtv = dt[(size_t)t * DINsz + d];
            const float xv  = xcs[(size_t)t * DINsz + d];
            __syncwarp();
            const float dtx = dtv * xv;
            const float r = __expf(dtv * An0);
            float p = r;
#pragma unroll
            for (int n = 0; n < NSTsz; n++) {
                h[n] = fmaf(h[n], p, dtx * sB[n]);
                p *= r;
            }
            S += dtv;
            __syncwarp();
        }
    } else {
        for (int l = 0; l < LCH; l++) {
            const int t = t0 + l;
            sB[lane] = xdbl[(size_t)t * 64 + DTRsz + lane];
            const float dtv = dt[(size_t)t * DINsz + d];
            const float xv  = xcs[(size_t)t * DINsz + d];
            __syncwarp();
            const float dtx = dtv * xv;
#pragma unroll
            for (int n = 0; n < NSTsz; n++)
                h[n] = fmaf(h[n], __expf(dtv * An[n]), dtx * sB[n]);
            S += dtv;
            __syncwarp();
        }
    }

    float* o = &g_hloc[((size_t)c * BDIM + bd) * NSTsz];
#pragma unroll
    for (int n = 0; n < NSTsz; n++) o[n] = h[n];
    g_S[(size_t)c * BDIM + bd] = S;
}

__global__ void scan_combine_kernel(const float* __restrict__ A_log)
{
    const int bd = blockIdx.x * blockDim.x + threadIdx.x;
    const int d = bd & (DINsz - 1);

    float An[NSTsz];
#pragma unroll
    for (int n = 0; n < NSTsz; n++) An[n] = -expf(A_log[d * NSTsz + n]);
    const float An0 = An[0];
    bool geo = true;
#pragma unroll
    for (int n = 0; n < NSTsz; n++) {
        float want = An0 * (n + 1);
        if (fabsf(An[n] - want) > 1e-5f * fabsf(want)) geo = false;
    }

    float H[NSTsz];
#pragma unroll
    for (int n = 0; n < NSTsz; n++) H[n] = 0.f;

    for (int c = 0; c < CCH; c++) {
        float* hs = &g_Hs[((size_t)c * BDIM + bd) * NSTsz];
#pragma unroll
        for (int n = 0; n < NSTsz; n++) hs[n] = H[n];

        const float S = g_S[(size_t)c * BDIM + bd];
        const float* hl = &g_hloc[((size_t)c * BDIM + bd) * NSTsz];
        if (geo) {
            const float R = __expf(S * An0);
            float p = R;
#pragma unroll
            for (int n = 0; n < NSTsz; n++) {
                H[n] = fmaf(H[n], p, hl[n]);
                p *= R;
            }
        } else {
#pragma unroll
            for (int n = 0; n < NSTsz; n++)
                H[n] = fmaf(H[n], __expf(S * An[n]), hl[n]);
        }
    }
}

__global__ void scan_final_kernel(const float* __restrict__ dt,
                                  const float* __restrict__ xdbl,
                                  const float* __restrict__ xcs,
                                  const float* __restrict__ xz,
                                  const float* __restrict__ A_log,
                                  const float* __restrict__ D_skip,
                                  __half* __restrict__ yh)
{
    const int b = blockIdx.y, c = blockIdx.z;
    const int lane = threadIdx.x;
    const int d = blockIdx.x * 32 + lane;
    const int bd = b * DINsz + d;

    float An[NSTsz];
#pragma unroll
    for (int n = 0; n < NSTsz; n++) An[n] = -expf(A_log[d * NSTsz + n]);
    const float An0 = An[0];
    bool geo = true;
#pragma unroll
    for (int n = 0; n < NSTsz; n++) {
        float want = An0 * (n + 1);
        if (fabsf(An[n] - want) > 1e-5f * fabsf(want)) geo = false;
    }

    float h[NSTsz];
    const float* hs = &g_Hs[((size_t)c * BDIM + bd) * NSTsz];
#pragma unroll
    for (int n = 0; n < NSTsz; n++) h[n] = hs[n];

    const float Dv = D_skip[d];
    __shared__ float sBC[32];
    const int t0 = b * Lsz + c * LCH;

    for (int l = 0; l < LCH; l++) {
        const int t = t0 + l;
        sBC[lane] = xdbl[(size_t)t * 64 + DTRsz + lane];
        const float dtv = dt[(size_t)t * DINsz + d];
        const float xv  = xcs[(size_t)t * DINsz + d];
        const float zv  = xz[(size_t)t * (2 * DINsz) + DINsz + d];
        __syncwarp();
        const float dtx = dtv * xv;
        float yv = 0.f;
        if (geo) {
            const float r = __expf(dtv * An0);
            float p = r;
#pragma unroll
            for (int n = 0; n < NSTsz; n++) {
                h[n] = fmaf(h[n], p, dtx * sBC[n]);
                yv = fmaf(h[n], sBC[NSTsz + n], yv);
                p *= r;
            }
        } else {
#pragma unroll
            for (int n = 0; n < NSTsz; n++) {
                h[n] = fmaf(h[n], __expf(dtv * An[n]), dtx * sBC[n]);
                yv = fmaf(h[n], sBC[NSTsz + n], yv);
            }
        }
        const float sz = zv / (1.f + __expf(-zv));
        const float o = (yv + Dv * xv) * sz;
        yh[(size_t)t * DINsz + d] = __float2half(o);
        __syncwarp();
    }
}

// ---------------- LayerNorm(512): fp32 in -> single fp16 out -------------------
__global__ void ln_kernel(const float* __restrict__ m,
                          const float* __restrict__ g,
                          const float* __restrict__ b,
                          __half* __restrict__ oh)
{
    const int warp = threadIdx.x >> 5;
    const int lane = threadIdx.x & 31;
    const int row = blockIdx.x * 8 + warp;

    const float4* p = (const float4*)(m + (size_t)row * BDsz);
    float4 v[4];
    float s = 0.f, ss = 0.f;
#pragma unroll
    for (int i = 0; i < 4; i++) {
        v[i] = p[lane + i * 32];
        s  += v[i].x + v[i].y + v[i].z + v[i].w;
        ss += v[i].x * v[i].x + v[i].y * v[i].y + v[i].z * v[i].z + v[i].w * v[i].w;
    }
#pragma unroll
    for (int o = 16; o > 0; o >>= 1) {
        s  += __shfl_xor_sync(0xFFFFFFFF, s, o);
        ss += __shfl_xor_sync(0xFFFFFFFF, ss, o);
    }
    const float mu = s * (1.f / BDsz);
    const float var = ss * (1.f / BDsz) - mu * mu;
    const float r = rsqrtf(var + 1e-5f);
#pragma unroll
    for (int i = 0; i < 4; i++) {
        int col = (lane + i * 32) * 4;
        float o0 = (v[i].x - mu) * r * __ldg(&g[col + 0]) + __ldg(&b[col + 0]);
        float o1 = (v[i].y - mu) * r * __ldg(&g[col + 1]) + __ldg(&b[col + 1]);
        float o2 = (v[i].z - mu) * r * __ldg(&g[col + 2]) + __ldg(&b[col + 2]);
        float o3 = (v[i].w - mu) * r * __ldg(&g[col + 3]) + __ldg(&b[col + 3]);
        __half2 h01 = __floats2half2_rn(o0, o1);
        __half2 h23 = __floats2half2_rn(o2, o3);
        *(uint2*)&oh[(size_t)row * BDsz + col] =
            make_uint2(*(uint32_t*)&h01, *(uint32_t*)&h23);
    }
}

// ------------------------------- launch ---------------------------------------
extern "C" void kernel_launch(void* const* d_in, const int* in_sizes, int n_in,
                              void* d_out, int out_size)
{
    const float* x      = (const float*)d_in[0];
    const float* W_down = (const float*)d_in[1];
    const float* b_down = (const float*)d_in[2];
    const float* W_in   = (const float*)d_in[3];
    const float* conv_w = (const float*)d_in[4];
    const float* conv_b = (const float*)d_in[5];
    const float* W_x    = (const float*)d_in[6];
    const float* W_dt   = (const float*)d_in[7];
    const float* b_dt   = (const float*)d_in[8];
    const float* A_log  = (const float*)d_in[9];
    const float* D_skip = (const float*)d_in[10];
    const float* W_out  = (const float*)d_in[11];
    const float* ln_g   = (const float*)d_in[12];
    const float* ln_b   = (const float*)d_in[13];
    const float* W_up   = (const float*)d_in[14];
    const float* b_up   = (const float*)d_in[15];
    float* out = (float*)d_out;

    float *pxz, *pxcs, *pxdbl, *pdt, *pm;
    cudaGetSymbolAddress((void**)&pxz,   g_xz);
    cudaGetSymbolAddress((void**)&pxcs,  g_xcs);
    cudaGetSymbolAddress((void**)&pxdbl, g_xdbl);
    cudaGetSymbolAddress((void**)&pdt,   g_dt);
    cudaGetSymbolAddress((void**)&pm,    g_m);

    __half *pxh, *phh, *pyh, *pmh;
    __half *pwd, *pwi, *pwo, *pwu;
    cudaGetSymbolAddress((void**)&pxh, g_xh);
    cudaGetSymbolAddress((void**)&phh, g_hh);
    cudaGetSymbolAddress((void**)&pyh, g_yh);
    cudaGetSymbolAddress((void**)&pmh, g_mh);
    cudaGetSymbolAddress((void**)&pwd, g_wd);
    cudaGetSymbolAddress((void**)&pwi, g_wi);
    cudaGetSymbolAddress((void**)&pwo, g_wo);
    cudaGetSymbolAddress((void**)&pwu, g_wu);

    const int M = Tsz;
    const int SM_SA = 1024 + 3 * 20480;   // 62464
    cudaFuncSetAttribute((const void*)hx_gemm<0>, cudaFuncAttributeMaxDynamicSharedMemorySize, SM_SA);
    cudaFuncSetAttribute((const void*)hx_gemm<1>, cudaFuncAttributeMaxDynamicSharedMemorySize, SM_SA);
    cudaFuncSetAttribute((const void*)hx_gemm<2>, cudaFuncAttributeMaxDynamicSharedMemorySize, SM_SA);

    dim3 tb(32, 8);

    // launch order keeps a big GEMM at index 3 for ncu capture
    // 0) x -> fp16
    split_kernel<<<(Tsz * Dsz) / (256 * 4), 256>>>(x, pxh);
    // 1) W_down^T
    tsplit_kernel<<<dim3(BDsz / 32, Dsz / 32), tb>>>(W_down, pwd, Dsz, BDsz);
    // 2) W_in^T
    tsplit_kernel<<<dim3(2 * DINsz / 32, BDsz / 32), tb>>>(W_in, pwi, BDsz, 2 * DINsz);

    // 3) GEMM1: h = x @ W_down + b_down -> single fp16   [PROFILED]
    hx_gemm<2><<<dim3(BDsz / 128, M / 128), 128, SM_SA>>>(
        M, BDsz, Dsz, pxh, pwd, b_down, nullptr, phh);

    // 4) W_out^T, 5) W_up^T
    tsplit_kernel<<<dim3(BDsz / 32, DINsz / 32), tb>>>(W_out, pwo, DINsz, BDsz);
    tsplit_kernel<<<dim3(Dsz / 32, BDsz / 32), tb>>>(W_up, pwu, BDsz, Dsz);

    // 6) GEMM2: xz = h @ W_in -> fp32
    hx_gemm<0><<<dim3(2 * DINsz / 128, M / 128), 128, SM_SA>>>(
        M, 2 * DINsz, BDsz, phh, pwi, nullptr, pxz, nullptr);

    // 7) conv + silu -> xcs
    conv_silu_kernel<<<(Tsz * DINsz) / 256, 256>>>(pxz, conv_w, conv_b, pxcs);

    // 8) x_dbl = xcs @ W_x
    mma_gemm<64, 32, 0><<<dim3(1, M / 128), 256>>>(
        M, 64, DINsz, DINsz, 64, 64, pxcs, W_x, nullptr, pxdbl);

    // 9) dt = softplus(x_dbl[:, :32] @ W_dt + b_dt)
    mma_gemm<128, 64, 2><<<dim3(DINsz / 128, M / 128), 256>>>(
        M, DINsz, DTRsz, 64, DINsz, DINsz, pxdbl, W_dt, b_dt, pdt);

    // 10-12) chunked scan -> y single fp16
    scan_chunk_kernel<<<dim3(DINsz / 32, Bsz, CCH), 32>>>(pdt, pxdbl, pxcs, A_log);
    scan_combine_kernel<<<BDIM / 256, 256>>>(A_log);
    scan_final_kernel<<<dim3(DINsz / 32, Bsz, CCH), 32>>>(
        pdt, pxdbl, pxcs, pxz, A_log, D_skip, pyh);

    // 13) GEMM7: m = y @ W_out -> fp32
    hx_gemm<0><<<dim3(BDsz / 128, M / 128), 128, SM_SA>>>(
        M, BDsz, DINsz, pyh, pwo, nullptr, pm, nullptr);

    // 14) LayerNorm -> single fp16
    ln_kernel<<<M / 8, 256>>>(pm, ln_g, ln_b, pmh);

    // 15) GEMM9: out = m_ln @ W_up + b_up -> fp32
    hx_gemm<1><<<dim3(Dsz / 128, M / 128), 128, SM_SA>>>(
        M, Dsz, BDsz, pmh, pwu, b_up, out, nullptr);
}